// round 13
// baseline (speedup 1.0000x reference)
#include <cuda_runtime.h>
#include <cuda_bf16.h>
#include <cstdint>

#define LN_EPS 1e-5f

// ---------------- scratch (device globals: allocation-free) ----------------
__device__ __align__(128) float g_y0[100000 * 64];    // layer0 gemm out only
__device__ __align__(128) float g_y1[100000 * 128];   // layer1 gemm out only
__device__ __align__(128) float g_y2[100000 * 256];   // layer2 gemm out only
__device__ __align__(128) __nv_bfloat16 g_w1thi0[64*64],  g_w1tlo0[64*64];
__device__ __align__(128) __nv_bfloat16 g_w1thi1[64*128], g_w1tlo1[64*128];
__device__ __align__(128) __nv_bfloat16 g_w1thi2[64*256], g_w1tlo2[64*256];
__device__ __align__(128) __nv_bfloat16 g_w2thi0[64*64],  g_w2tlo0[64*64];
__device__ __align__(128) __nv_bfloat16 g_w2thi1[128*64], g_w2tlo1[128*64];
__device__ __align__(128) __nv_bfloat16 g_w2thi2[256*64], g_w2tlo2[256*64];
__device__ float g_colsq[512];

// CSR scratch
__device__ int g_deg[100000];
__device__ int g_rowptr[100000];
__device__ int g_cursor[100000];
__device__ int g_esrc[800000];
__device__ int g_cdeg[10000];
__device__ int g_cptr[10000];
__device__ int g_ccur[10000];
__device__ int g_cnodes[100000];
__device__ int g_bsumsN[512];
__device__ int g_bsumsC[512];

__device__ __forceinline__ float neg_inf() { return __int_as_float(0xff800000); }

__device__ __forceinline__ void split2(float a, float b, uint32_t& hi, uint32_t& lo) {
    __nv_bfloat16 ah = __float2bfloat16_rn(a);
    __nv_bfloat16 bh = __float2bfloat16_rn(b);
    __nv_bfloat16 al = __float2bfloat16_rn(a - __bfloat162float(ah));
    __nv_bfloat16 bl = __float2bfloat16_rn(b - __bfloat162float(bh));
    __nv_bfloat162 h = __halves2bfloat162(ah, bh);
    __nv_bfloat162 l = __halves2bfloat162(al, bl);
    hi = *reinterpret_cast<uint32_t*>(&h);
    lo = *reinterpret_cast<uint32_t*>(&l);
}

__device__ __forceinline__ void mma16816(float* c, const uint32_t* a,
                                         uint32_t b0, uint32_t b1) {
    asm volatile(
        "mma.sync.aligned.m16n8k16.row.col.f32.bf16.bf16.f32 "
        "{%0,%1,%2,%3}, {%4,%5,%6,%7}, {%8,%9}, {%0,%1,%2,%3};"
        : "+f"(c[0]), "+f"(c[1]), "+f"(c[2]), "+f"(c[3])
        : "r"(a[0]), "r"(a[1]), "r"(a[2]), "r"(a[3]), "r"(b0), "r"(b1));
}

__device__ __forceinline__ uint32_t sm_off(const void* p) {
    uint32_t a;
    asm("{ .reg .u64 t; cvta.to.shared.u64 t, %1; cvt.u32.u64 %0, t; }" : "=r"(a) : "l"(p));
    return a;
}

__device__ __forceinline__ void ldsm_x4(uint32_t& r0, uint32_t& r1,
                                        uint32_t& r2, uint32_t& r3, uint32_t addr) {
    asm volatile("ldmatrix.sync.aligned.m8n8.x4.shared.b16 {%0,%1,%2,%3}, [%4];"
                 : "=r"(r0), "=r"(r1), "=r"(r2), "=r"(r3) : "r"(addr));
}

// ---------------- init: zero CSR counters + convert all weights -------------
struct WConv {
    const float* in[6];
    __nv_bfloat16* hi[6];
    __nv_bfloat16* lo[6];
    int K[6], M[6];
    int off[7];
};

__global__ void init_misc(WConv a, int* __restrict__ deg, int* __restrict__ cursor,
                          int* __restrict__ cdeg, int* __restrict__ ccur,
                          float* __restrict__ colsq, int n, int nc)
{
    int gid = blockIdx.x * blockDim.x + threadIdx.x;
    if (gid < n) { deg[gid] = 0; cursor[gid] = 0; }
    if (gid < nc) { cdeg[gid] = 0; ccur[gid] = 0; }
    if (gid < 512) colsq[gid] = 0.f;
    if (gid < a.off[6]) {
        int s = 0;
#pragma unroll
        for (int i = 1; i < 6; i++) if (gid >= a.off[i]) s = i;
        int local = gid - a.off[s];
        int M = a.M[s], K = a.K[s];
        int k = local / M, m = local - k * M;
        float v = __ldg(a.in[s] + local);
        __nv_bfloat16 h = __float2bfloat16_rn(v);
        a.hi[s][m * K + k] = h;
        a.lo[s][m * K + k] = __float2bfloat16_rn(v - __bfloat162float(h));
    }
}

// ---------------- CSR build --------------------------------------------------
__global__ void hist_fused(const int* __restrict__ ei, int E,
                           const int* __restrict__ cluster, int n,
                           int* __restrict__ deg, int* __restrict__ cdeg)
{
    int gid = blockIdx.x * blockDim.x + threadIdx.x;
    if (gid < E) {
        atomicAdd(&deg[__ldg(ei + E + gid)], 1);
    } else if (gid < E + n) {
        atomicAdd(&cdeg[__ldg(cluster + gid - E)], 1);
    }
}

__global__ __launch_bounds__(512) void scan_block2(
    const int* __restrict__ inN, int* __restrict__ outN, int* __restrict__ sumsN, int n, int nbN,
    const int* __restrict__ inC, int* __restrict__ outC, int* __restrict__ sumsC, int nc)
{
    __shared__ int s[512];
    int tid = threadIdx.x;
    const int* in;  int* out; int* sums; int len; int blk;
    if ((int)blockIdx.x < nbN) { in = inN; out = outN; sums = sumsN; len = n;  blk = blockIdx.x; }
    else                       { in = inC; out = outC; sums = sumsC; len = nc; blk = blockIdx.x - nbN; }
    int i = blk * 512 + tid;
    int v = (i < len) ? in[i] : 0;
    s[tid] = v;
    __syncthreads();
#pragma unroll
    for (int off = 1; off < 512; off <<= 1) {
        int t = (tid >= off) ? s[tid - off] : 0;
        __syncthreads();
        s[tid] += t;
        __syncthreads();
    }
    if (i < len) out[i] = s[tid] - v;
    if (tid == 511) sums[blk] = s[511];
}

__global__ __launch_bounds__(512) void scan_add_fused(
    int* __restrict__ outN, const int* __restrict__ sumsN, int n, int nbN,
    int* __restrict__ outC, const int* __restrict__ sumsC, int nc)
{
    __shared__ int red[16];
    __shared__ int total;
    int tid = threadIdx.x;
    int* out; const int* sums; int len; int blk;
    if ((int)blockIdx.x < nbN) { out = outN; sums = sumsN; len = n;  blk = blockIdx.x; }
    else                       { out = outC; sums = sumsC; len = nc; blk = blockIdx.x - nbN; }
    int p = 0;
    for (int i = tid; i < blk; i += 512) p += sums[i];
#pragma unroll
    for (int off = 16; off >= 1; off >>= 1) p += __shfl_xor_sync(0xffffffffu, p, off);
    if ((tid & 31) == 0) red[tid >> 5] = p;
    __syncthreads();
    if (tid == 0) {
        int t = 0;
#pragma unroll
        for (int i = 0; i < 16; i++) t += red[i];
        total = t;
    }
    __syncthreads();
    int i = blk * 512 + tid;
    if (i < len) out[i] += total;
}

__global__ void scatter_fused(const int* __restrict__ ei, int E,
                              const int* __restrict__ cluster, int n,
                              const int* __restrict__ rowptr, int* __restrict__ cursor,
                              int* __restrict__ esrc,
                              const int* __restrict__ cptr, int* __restrict__ ccur,
                              int* __restrict__ cnodes)
{
    int gid = blockIdx.x * blockDim.x + threadIdx.x;
    if (gid < E) {
        int src = __ldg(ei + gid);
        int tgt = __ldg(ei + E + gid);
        int pos = rowptr[tgt] + atomicAdd(&cursor[tgt], 1);
        esrc[pos] = src;
    } else if (gid < E + n) {
        int i = gid - E;
        int cl = __ldg(cluster + i);
        int pos = cptr[cl] + atomicAdd(&ccur[cl], 1);
        cnodes[pos] = i;
    }
}

// ---------------- fused MLP layer (with optional in-staging agg gather) -----
// GATHER=false: Ain [n, C] fp32 (full concat rows).
// GATHER=true:  Ain [n, C/2] fp32 (gemm half); concat cols [C/2,C) are computed
//               on the fly as neighbor-max of Ain rows (CSR gather).
// W1T [64][C] split bf16, W2T [C][64] split bf16.
// Y row stride OS floats; first C_out=C cols of gemm2 written there.
template<int C, int OS, bool GATHER>
__global__ __launch_bounds__(256) void fused_mlp(
    const float* __restrict__ Ain,
    const int* __restrict__ rowptr, const int* __restrict__ deg,
    const int* __restrict__ esrc,
    const __nv_bfloat16* __restrict__ W1hi, const __nv_bfloat16* __restrict__ W1lo,
    const float* __restrict__ b1, const float* __restrict__ gam,
    const float* __restrict__ bet,
    const __nv_bfloat16* __restrict__ W2hi, const __nv_bfloat16* __restrict__ W2lo,
    const float* __restrict__ b2,
    float* __restrict__ Y, int n)
{
    constexpr int AS   = 72;
    constexpr int WS   = C + 8;
    constexpr int NKC  = C / 64;
    constexpr int ND   = GATHER ? NKC / 2 : NKC;   // direct chunks (first ND)
    constexpr int ISF2 = (GATHER ? C / 2 : C) / 2; // input stride in float2
    constexpr int NG   = C / 64;
    constexpr int W1E  = 64 * WS;
    constexpr int AE   = 128 * AS;
    extern __shared__ __align__(16) __nv_bfloat16 sm[];
    __nv_bfloat16* W1s0 = sm;
    __nv_bfloat16* W1s1 = sm + W1E;
    __nv_bfloat16* As0  = sm + 2 * W1E;
    __nv_bfloat16* As1  = As0 + AE;
    __nv_bfloat16* W2s0 = As1 + AE;
    __nv_bfloat16* W2s1 = W2s0 + C * AS;

    const int tid = threadIdx.x, wid = tid >> 5, lane = tid & 31;
    const int g = lane >> 2, q = lane & 3;
    const int r0b = blockIdx.x * 128;

    // load weights (W1 + W2 up front)
    {
        constexpr int VPR = C / 8;
        for (int i = tid; i < 64 * VPR; i += 256) {
            int m = i / VPR, seg = i - m * VPR;
            *(uint4*)&W1s0[m * WS + seg * 8] = __ldg((const uint4*)(W1hi + (size_t)m * C) + seg);
            *(uint4*)&W1s1[m * WS + seg * 8] = __ldg((const uint4*)(W1lo + (size_t)m * C) + seg);
        }
        for (int i = tid; i < C * 8; i += 256) {
            int m = i >> 3, seg = i & 7;
            *(uint4*)&W2s0[m * AS + seg * 8] = __ldg((const uint4*)(W2hi + (size_t)m * 64) + seg);
            *(uint4*)&W2s1[m * AS + seg * 8] = __ldg((const uint4*)(W2lo + (size_t)m * 64) + seg);
        }
    }

    // per-thread ldmatrix address bases
    const int arow = wid * 16 + (lane & 15);
    const int acol = ((lane >> 4) & 1) * 8;
    const uint32_t a_hi = sm_off(As0 + arow * AS + acol);
    const uint32_t a_lo = sm_off(As1 + arow * AS + acol);
    const int brow = (lane & 7) + ((lane >> 4) << 3);
    const int bk8  = ((lane >> 3) & 1) * 8;
    const uint32_t w1h_b = sm_off(W1s0 + brow * WS + bk8);
    const uint32_t w1l_b = sm_off(W1s1 + brow * WS + bk8);
    const uint32_t w2h_b = sm_off(W2s0 + brow * AS + bk8);
    const uint32_t w2l_b = sm_off(W2s1 + brow * AS + bk8);

    // staging map: warp w handles rows w, w+8, ..., w+120; lane = float2 col
    const int sm_m = tid >> 5;
    const int sm_e = tid & 31;

    float acc[8][4] = {};

    // stage chunk 0 (always direct)
    {
#pragma unroll
        for (int rpt = 0; rpt < 16; rpt++) {
            int m = sm_m + rpt * 8;
            int r = r0b + m;
            uint32_t h = 0, l = 0;
            if (r < n) {
                float2 v = __ldg((const float2*)Ain + (size_t)r * ISF2 + sm_e);
                split2(v.x, v.y, h, l);
            }
            *(uint32_t*)&As0[m * AS + 2 * sm_e] = h;
            *(uint32_t*)&As1[m * AS + 2 * sm_e] = l;
        }
    }
    __syncthreads();

    for (int kc = 0; kc < NKC; kc++) {
        // prefetch chunk kc+1 into registers (overlaps with MMA below)
        float2 pf[16];
        if (kc + 1 < NKC) {
            if (!GATHER || kc + 1 < ND) {
#pragma unroll
                for (int rpt = 0; rpt < 16; rpt++) {
                    int m = sm_m + rpt * 8;
                    int r = r0b + m;
                    pf[rpt] = (r < n)
                        ? __ldg((const float2*)Ain + (size_t)r * ISF2 + (kc + 1) * 32 + sm_e)
                        : make_float2(0.f, 0.f);
                }
            } else {
                // gather chunk: neighbor-max of Ain rows, col base (kc+1-ND)*32 f2
                const int cb2 = (kc + 1 - ND) * 32 + sm_e;
#pragma unroll
                for (int rpt = 0; rpt < 16; rpt++) {
                    int m = sm_m + rpt * 8;
                    int r = r0b + m;
                    float2 mx = make_float2(neg_inf(), neg_inf());
                    int d = 0;
                    if (r < n) {
                        d = __ldg(deg + r);
                        int b = __ldg(rowptr + r);
                        int j = 0;
                        for (; j + 1 < d; j += 2) {
                            int s0 = __ldg(esrc + b + j);
                            int s1 = __ldg(esrc + b + j + 1);
                            float2 v0 = __ldg((const float2*)Ain + (size_t)s0 * ISF2 + cb2);
                            float2 v1 = __ldg((const float2*)Ain + (size_t)s1 * ISF2 + cb2);
                            mx.x = fmaxf(mx.x, fmaxf(v0.x, v1.x));
                            mx.y = fmaxf(mx.y, fmaxf(v0.y, v1.y));
                        }
                        if (j < d) {
                            int s0 = __ldg(esrc + b + j);
                            float2 v0 = __ldg((const float2*)Ain + (size_t)s0 * ISF2 + cb2);
                            mx.x = fmaxf(mx.x, v0.x);
                            mx.y = fmaxf(mx.y, v0.y);
                        }
                    }
                    pf[rpt] = d ? mx : make_float2(0.f, 0.f);
                }
            }
        }

#pragma unroll
        for (int ks = 0; ks < 4; ks++) {
            const int k0 = ks * 16;
            uint32_t ah[4], al[4];
            ldsm_x4(ah[0], ah[1], ah[2], ah[3], a_hi + k0 * 2);
            ldsm_x4(al[0], al[1], al[2], al[3], a_lo + k0 * 2);
            const int kg = kc * 64 + k0;
#pragma unroll
            for (int jj = 0; jj < 8; jj += 2) {
                uint32_t p0, p1, p2, p3, l0, l1, l2, l3;
                ldsm_x4(p0, p1, p2, p3, w1h_b + (8 * jj * WS + kg) * 2);
                ldsm_x4(l0, l1, l2, l3, w1l_b + (8 * jj * WS + kg) * 2);
                mma16816(acc[jj],     ah, p0, p1);
                mma16816(acc[jj],     ah, l0, l1);
                mma16816(acc[jj],     al, p0, p1);
                mma16816(acc[jj + 1], ah, p2, p3);
                mma16816(acc[jj + 1], ah, l2, l3);
                mma16816(acc[jj + 1], al, p2, p3);
            }
        }

        if (kc + 1 < NKC) {
            __syncthreads();     // all MMA reads of As done
#pragma unroll
            for (int rpt = 0; rpt < 16; rpt++) {
                int m = sm_m + rpt * 8;
                uint32_t h, l;
                split2(pf[rpt].x, pf[rpt].y, h, l);
                *(uint32_t*)&As0[m * AS + 2 * sm_e] = h;
                *(uint32_t*)&As1[m * AS + 2 * sm_e] = l;
            }
            __syncthreads();
        }
    }

    // ---- gemm1 epilogue: bias + LN (quad shuffle) + ReLU -> H in As --------
    {
        float v0[16], v1[16];
        float s0 = 0.f, q0 = 0.f, s1 = 0.f, q1 = 0.f;
#pragma unroll
        for (int j = 0; j < 8; j++) {
            int c0 = 8*j + 2*q;
            float bx = __ldg(b1 + c0), by = __ldg(b1 + c0 + 1);
            float a = acc[j][0] + bx, b = acc[j][1] + by;
            float c = acc[j][2] + bx, d = acc[j][3] + by;
            v0[2*j] = a; v0[2*j+1] = b; v1[2*j] = c; v1[2*j+1] = d;
            s0 += a + b; q0 += a*a + b*b;
            s1 += c + d; q1 += c*c + d*d;
        }
#pragma unroll
        for (int off = 1; off < 4; off <<= 1) {
            s0 += __shfl_xor_sync(0xffffffffu, s0, off);
            q0 += __shfl_xor_sync(0xffffffffu, q0, off);
            s1 += __shfl_xor_sync(0xffffffffu, s1, off);
            q1 += __shfl_xor_sync(0xffffffffu, q1, off);
        }
        float mu0 = s0 * (1.f/64.f), var0 = q0 * (1.f/64.f) - mu0*mu0;
        float mu1 = s1 * (1.f/64.f), var1 = q1 * (1.f/64.f) - mu1*mu1;
        float rs0 = rsqrtf(var0 + LN_EPS), rs1 = rsqrtf(var1 + LN_EPS);
        __syncthreads();
        int rl0 = wid * 16 + g, rl1 = rl0 + 8;
#pragma unroll
        for (int j = 0; j < 8; j++) {
            int c0 = 8*j + 2*q;
            float ga = __ldg(gam + c0), gb = __ldg(gam + c0 + 1);
            float ba = __ldg(bet + c0), bb = __ldg(bet + c0 + 1);
            float f0 = fmaxf((v0[2*j]   - mu0) * rs0 * ga + ba, 0.f);
            float f1 = fmaxf((v0[2*j+1] - mu0) * rs0 * gb + bb, 0.f);
            float f2 = fmaxf((v1[2*j]   - mu1) * rs1 * ga + ba, 0.f);
            float f3 = fmaxf((v1[2*j+1] - mu1) * rs1 * gb + bb, 0.f);
            uint32_t h, l;
            split2(f0, f1, h, l);
            *(uint32_t*)&As0[rl0 * AS + c0] = h;
            *(uint32_t*)&As1[rl0 * AS + c0] = l;
            split2(f2, f3, h, l);
            *(uint32_t*)&As0[rl1 * AS + c0] = h;
            *(uint32_t*)&As1[rl1 * AS + c0] = l;
        }
    }
    __syncthreads();

    // ---- gemm2: H[128,64] @ W2 -> Y[:, 0:C] --------------------------------
    const int rg0 = r0b + wid * 16 + g;
    const int rg1 = rg0 + 8;

#pragma unroll
    for (int ng = 0; ng < NG; ng++) {
        float acc2[8][4] = {};
#pragma unroll
        for (int ks = 0; ks < 4; ks++) {
            const int k0 = ks * 16;
            uint32_t ah[4], al[4];
            ldsm_x4(ah[0], ah[1], ah[2], ah[3], a_hi + k0 * 2);
            ldsm_x4(al[0], al[1], al[2], al[3], a_lo + k0 * 2);
#pragma unroll
            for (int jj = 0; jj < 8; jj += 2) {
                uint32_t p0, p1, p2, p3, l0, l1, l2, l3;
                ldsm_x4(p0, p1, p2, p3, w2h_b + ((ng * 64 + 8 * jj) * AS + k0) * 2);
                ldsm_x4(l0, l1, l2, l3, w2l_b + ((ng * 64 + 8 * jj) * AS + k0) * 2);
                mma16816(acc2[jj],     ah, p0, p1);
                mma16816(acc2[jj],     ah, l0, l1);
                mma16816(acc2[jj],     al, p0, p1);
                mma16816(acc2[jj + 1], ah, p2, p3);
                mma16816(acc2[jj + 1], ah, l2, l3);
                mma16816(acc2[jj + 1], al, p2, p3);
            }
        }
        if (rg0 < n) {
            float2* orow = (float2*)(Y + (size_t)rg0 * OS) + ng * 32;
#pragma unroll
            for (int j = 0; j < 8; j++) {
                int c0 = 8*j + 2*q;
                orow[4*j + q] = make_float2(acc2[j][0] + __ldg(b2 + ng*64 + c0),
                                            acc2[j][1] + __ldg(b2 + ng*64 + c0 + 1));
            }
        }
        if (rg1 < n) {
            float2* orow = (float2*)(Y + (size_t)rg1 * OS) + ng * 32;
#pragma unroll
            for (int j = 0; j < 8; j++) {
                int c0 = 8*j + 2*q;
                orow[4*j + q] = make_float2(acc2[j][2] + __ldg(b2 + ng*64 + c0),
                                            acc2[j][3] + __ldg(b2 + ng*64 + c0 + 1));
            }
        }
    }
}

// ---------------- fused layer-2 agg + cluster max-pool ----------------------
__global__ __launch_bounds__(128) void pool_agg(
    const float* __restrict__ Y,
    const int* __restrict__ cptr, const int* __restrict__ cdeg,
    const int* __restrict__ cnodes,
    const int* __restrict__ rowptr, const int* __restrict__ deg,
    const int* __restrict__ esrc,
    float* __restrict__ out)
{
    int cl = blockIdx.x, t = threadIdx.x;
    int cd = __ldg(cdeg + cl), cbase = __ldg(cptr + cl);
    float2 m0 = make_float2(neg_inf(), neg_inf());
    float2 m1 = m0;
    bool zerodeg = false;
    for (int j = 0; j < cd; j++) {
        int nd = __ldg(cnodes + cbase + j);
        const float2* row = (const float2*)(Y + (size_t)nd * 256);
        float2 v = __ldg(row + t);
        m0.x = fmaxf(m0.x, v.x); m0.y = fmaxf(m0.y, v.y);
        int d = __ldg(deg + nd), eb = __ldg(rowptr + nd);
        if (d == 0) zerodeg = true;
        int e = 0;
        for (; e + 1 < d; e += 2) {
            int s0 = __ldg(esrc + eb + e);
            int s1 = __ldg(esrc + eb + e + 1);
            float2 w0 = __ldg((const float2*)(Y + (size_t)s0 * 256) + t);
            float2 w1 = __ldg((const float2*)(Y + (size_t)s1 * 256) + t);
            m1.x = fmaxf(m1.x, fmaxf(w0.x, w1.x));
            m1.y = fmaxf(m1.y, fmaxf(w0.y, w1.y));
        }
        if (e < d) {
            int s0 = __ldg(esrc + eb + e);
            float2 w0 = __ldg((const float2*)(Y + (size_t)s0 * 256) + t);
            m1.x = fmaxf(m1.x, w0.x);
            m1.y = fmaxf(m1.y, w0.y);
        }
    }
    if (cd == 0) {
        m0 = make_float2(0.f, 0.f);
        m1 = m0;
    } else if (zerodeg) {
        m1.x = fmaxf(m1.x, 0.f);
        m1.y = fmaxf(m1.y, 0.f);
    }
    float2* orow = (float2*)(out + (size_t)cl * 512);
    orow[t] = m0;
    orow[t + 128] = m1;
}

// ---------------- column L2 normalize ---------------------------------------
__global__ __launch_bounds__(512) void colsq_kernel(const float* __restrict__ out,
                                                    float* __restrict__ colsq, int nc)
{
    const int ROWS = 50;
    int c  = threadIdx.x;
    int r0 = blockIdx.x * ROWS;
    int r1 = min(r0 + ROWS, nc);
    float s = 0.f;
    for (int r = r0; r < r1; r++) {
        float f = out[(size_t)r * 512 + c];
        s += f * f;
    }
    atomicAdd(colsq + c, s);
}

__global__ void scale_kernel(float* __restrict__ out, const float* __restrict__ colsq, int nc)
{
    int gid = blockIdx.x * blockDim.x + threadIdx.x;
    if (gid >= nc * 128) return;
    int c4 = gid & 127;
    float4 v = *(float4*)(out + (size_t)gid * 4);
    float4 s = *(const float4*)(colsq + c4 * 4);
    v.x *= rsqrtf(s.x); v.y *= rsqrtf(s.y);
    v.z *= rsqrtf(s.z); v.w *= rsqrtf(s.w);
    *(float4*)(out + (size_t)gid * 4) = v;
}

// ---------------- launch ----------------------------------------------------
extern "C" void kernel_launch(void* const* d_in, const int* in_sizes, int n_in,
                              void* d_out, int out_size)
{
    const float* x       = (const float*)d_in[0];
    const int*   ei      = (const int*)d_in[1];
    const int*   cluster = (const int*)d_in[2];
    const int N  = in_sizes[0] / 64;
    const int E  = in_sizes[1] / 2;
    const int NC = out_size / 512;
    float* out = (float*)d_out;

    float *y0, *y1, *y2, *colsq;
    __nv_bfloat16 *w1h[3], *w1l[3], *w2h[3], *w2l[3];
    int *deg, *rowptr, *cursor, *esrc, *cdeg, *cptr, *ccur, *cnodes, *bsumsN, *bsumsC;
    cudaGetSymbolAddress((void**)&y0, g_y0);
    cudaGetSymbolAddress((void**)&y1, g_y1);
    cudaGetSymbolAddress((void**)&y2, g_y2);
    cudaGetSymbolAddress((void**)&w1h[0], g_w1thi0); cudaGetSymbolAddress((void**)&w1l[0], g_w1tlo0);
    cudaGetSymbolAddress((void**)&w1h[1], g_w1thi1); cudaGetSymbolAddress((void**)&w1l[1], g_w1tlo1);
    cudaGetSymbolAddress((void**)&w1h[2], g_w1thi2); cudaGetSymbolAddress((void**)&w1l[2], g_w1tlo2);
    cudaGetSymbolAddress((void**)&w2h[0], g_w2thi0); cudaGetSymbolAddress((void**)&w2l[0], g_w2tlo0);
    cudaGetSymbolAddress((void**)&w2h[1], g_w2thi1); cudaGetSymbolAddress((void**)&w2l[1], g_w2tlo1);
    cudaGetSymbolAddress((void**)&w2h[2], g_w2thi2); cudaGetSymbolAddress((void**)&w2l[2], g_w2tlo2);
    cudaGetSymbolAddress((void**)&colsq,  g_colsq);
    cudaGetSymbolAddress((void**)&deg,    g_deg);
    cudaGetSymbolAddress((void**)&rowptr, g_rowptr);
    cudaGetSymbolAddress((void**)&cursor, g_cursor);
    cudaGetSymbolAddress((void**)&esrc,   g_esrc);
    cudaGetSymbolAddress((void**)&cdeg,   g_cdeg);
    cudaGetSymbolAddress((void**)&cptr,   g_cptr);
    cudaGetSymbolAddress((void**)&ccur,   g_ccur);
    cudaGetSymbolAddress((void**)&cnodes, g_cnodes);
    cudaGetSymbolAddress((void**)&bsumsN, g_bsumsN);
    cudaGetSymbolAddress((void**)&bsumsC, g_bsumsC);

    const int SM64  = 2 * (64*72  + 128*72 + 64*72 ) * 2;   //  73728
    const int SM128 = 2 * (64*136 + 128*72 + 128*72) * 2;   // 108544
    const int SM256 = 2 * (64*264 + 128*72 + 256*72) * 2;   // 178176
    cudaFuncSetAttribute((const void*)fused_mlp<64, 64, false>,  cudaFuncAttributeMaxDynamicSharedMemorySize, SM64);
    cudaFuncSetAttribute((const void*)fused_mlp<128, 128, true>, cudaFuncAttributeMaxDynamicSharedMemorySize, SM128);
    cudaFuncSetAttribute((const void*)fused_mlp<256, 256, true>, cudaFuncAttributeMaxDynamicSharedMemorySize, SM256);

    const int GRID = (N + 127) / 128;
    const int nbN = (N + 511) / 512;
    const int nbC = (NC + 511) / 512;

    // ---- init: zero counters + weight conversion (1 launch) ----
    {
        WConv a;
        int off = 0;
        const int CINs[3] = {64, 128, 256};
        for (int i = 0; i < 3; i++) {
            int c = CINs[i];
            a.in[2*i]   = (const float*)d_in[3 + 6*i];
            a.hi[2*i]   = w1h[i]; a.lo[2*i] = w1l[i];
            a.K[2*i]    = c;  a.M[2*i] = 64;
            a.off[2*i]  = off; off += c * 64;
            a.in[2*i+1] = (const float*)d_in[3 + 6*i + 4];
            a.hi[2*i+1] = w2h[i]; a.lo[2*i+1] = w2l[i];
            a.K[2*i+1]  = 64; a.M[2*i+1] = c;
            a.off[2*i+1] = off; off += 64 * c;
        }
        a.off[6] = off;
        int span = N > off ? N : off;
        init_misc<<<(span + 255) / 256, 256>>>(a, deg, cursor, cdeg, ccur, colsq, N, NC);
    }

    // ---- CSR build (4 launches) ----
    hist_fused<<<(E + N + 255) / 256, 256>>>(ei, E, cluster, N, deg, cdeg);
    scan_block2<<<nbN + nbC, 512>>>(deg, rowptr, bsumsN, N, nbN, cdeg, cptr, bsumsC, NC);
    scan_add_fused<<<nbN + nbC, 512>>>(rowptr, bsumsN, N, nbN, cptr, bsumsC, NC);
    scatter_fused<<<(E + N + 255) / 256, 256>>>(ei, E, cluster, N, rowptr, cursor, esrc,
                                                cptr, ccur, cnodes);

    // ---- layers (agg fused into next layer's staging) ----
    fused_mlp<64, 64, false><<<GRID, 256, SM64>>>(
        x, nullptr, nullptr, nullptr,
        w1h[0], w1l[0], (const float*)d_in[4], (const float*)d_in[5],
        (const float*)d_in[6], w2h[0], w2l[0], (const float*)d_in[8], y0, N);

    fused_mlp<128, 128, true><<<GRID, 256, SM128>>>(
        y0, rowptr, deg, esrc,
        w1h[1], w1l[1], (const float*)d_in[10], (const float*)d_in[11],
        (const float*)d_in[12], w2h[1], w2l[1], (const float*)d_in[14], y1, N);

    fused_mlp<256, 256, true><<<GRID, 256, SM256>>>(
        y1, rowptr, deg, esrc,
        w1h[2], w1l[2], (const float*)d_in[16], (const float*)d_in[17],
        (const float*)d_in[18], w2h[2], w2l[2], (const float*)d_in[20], y2, N);

    // ---- fused layer-2 agg + cluster max-pool + column L2 normalize ----
    pool_agg<<<NC, 128>>>(y2, cptr, cdeg, cnodes, rowptr, deg, esrc, out);
    colsq_kernel<<<(NC + 49) / 50, 512>>>(out, colsq, NC);
    scale_kernel<<<(NC * 128 + 255) / 256, 256>>>(out, colsq, NC);
}

// round 14
// speedup vs baseline: 1.4381x; 1.4381x over previous
#include <cuda_runtime.h>
#include <cuda_bf16.h>
#include <cstdint>

#define LN_EPS 1e-5f

// ---------------- scratch (device globals: allocation-free) ----------------
__device__ __align__(128) float g_y0[100000 * 128];
__device__ __align__(128) float g_y1[100000 * 256];
__device__ __align__(128) float g_y2[100000 * 256];   // layer2 GEMM out only
__device__ __align__(128) __nv_bfloat16 g_w1thi0[64*64],  g_w1tlo0[64*64];
__device__ __align__(128) __nv_bfloat16 g_w1thi1[64*128], g_w1tlo1[64*128];
__device__ __align__(128) __nv_bfloat16 g_w1thi2[64*256], g_w1tlo2[64*256];
__device__ __align__(128) __nv_bfloat16 g_w2thi0[64*64],  g_w2tlo0[64*64];
__device__ __align__(128) __nv_bfloat16 g_w2thi1[128*64], g_w2tlo1[128*64];
__device__ __align__(128) __nv_bfloat16 g_w2thi2[256*64], g_w2tlo2[256*64];
__device__ float g_colsq[512];

// CSR scratch
__device__ int g_deg[100000];
__device__ int g_rowptr[100000];
__device__ int g_cursor[100000];
__device__ int g_esrc[800000];
__device__ int g_cdeg[10000];
__device__ int g_cptr[10000];
__device__ int g_ccur[10000];
__device__ int g_cnodes[100000];
__device__ int g_bsumsN[512];
__device__ int g_bsumsC[512];

__device__ __forceinline__ float neg_inf() { return __int_as_float(0xff800000); }

__device__ __forceinline__ void split2(float a, float b, uint32_t& hi, uint32_t& lo) {
    __nv_bfloat16 ah = __float2bfloat16_rn(a);
    __nv_bfloat16 bh = __float2bfloat16_rn(b);
    __nv_bfloat16 al = __float2bfloat16_rn(a - __bfloat162float(ah));
    __nv_bfloat16 bl = __float2bfloat16_rn(b - __bfloat162float(bh));
    __nv_bfloat162 h = __halves2bfloat162(ah, bh);
    __nv_bfloat162 l = __halves2bfloat162(al, bl);
    hi = *reinterpret_cast<uint32_t*>(&h);
    lo = *reinterpret_cast<uint32_t*>(&l);
}

__device__ __forceinline__ void mma16816(float* c, const uint32_t* a,
                                         uint32_t b0, uint32_t b1) {
    asm volatile(
        "mma.sync.aligned.m16n8k16.row.col.f32.bf16.bf16.f32 "
        "{%0,%1,%2,%3}, {%4,%5,%6,%7}, {%8,%9}, {%0,%1,%2,%3};"
        : "+f"(c[0]), "+f"(c[1]), "+f"(c[2]), "+f"(c[3])
        : "r"(a[0]), "r"(a[1]), "r"(a[2]), "r"(a[3]), "r"(b0), "r"(b1));
}

__device__ __forceinline__ uint32_t sm_off(const void* p) {
    uint32_t a;
    asm("{ .reg .u64 t; cvta.to.shared.u64 t, %1; cvt.u32.u64 %0, t; }" : "=r"(a) : "l"(p));
    return a;
}

__device__ __forceinline__ void ldsm_x4(uint32_t& r0, uint32_t& r1,
                                        uint32_t& r2, uint32_t& r3, uint32_t addr) {
    asm volatile("ldmatrix.sync.aligned.m8n8.x4.shared.b16 {%0,%1,%2,%3}, [%4];"
                 : "=r"(r0), "=r"(r1), "=r"(r2), "=r"(r3) : "r"(addr));
}

// ---------------- init: zero CSR counters + convert all weights -------------
struct WConv {
    const float* in[6];
    __nv_bfloat16* hi[6];
    __nv_bfloat16* lo[6];
    int K[6], M[6];
    int off[7];
};

__global__ void init_misc(WConv a, int* __restrict__ deg, int* __restrict__ cursor,
                          int* __restrict__ cdeg, int* __restrict__ ccur,
                          float* __restrict__ colsq, int n, int nc)
{
    int gid = blockIdx.x * blockDim.x + threadIdx.x;
    if (gid < n) { deg[gid] = 0; cursor[gid] = 0; }
    if (gid < nc) { cdeg[gid] = 0; ccur[gid] = 0; }
    if (gid < 512) colsq[gid] = 0.f;
    if (gid < a.off[6]) {
        int s = 0;
#pragma unroll
        for (int i = 1; i < 6; i++) if (gid >= a.off[i]) s = i;
        int local = gid - a.off[s];
        int M = a.M[s], K = a.K[s];
        int k = local / M, m = local - k * M;
        float v = __ldg(a.in[s] + local);
        __nv_bfloat16 h = __float2bfloat16_rn(v);
        a.hi[s][m * K + k] = h;
        a.lo[s][m * K + k] = __float2bfloat16_rn(v - __bfloat162float(h));
    }
}

// ---------------- CSR build --------------------------------------------------
__global__ void hist_fused(const int* __restrict__ ei, int E,
                           const int* __restrict__ cluster, int n,
                           int* __restrict__ deg, int* __restrict__ cdeg)
{
    int gid = blockIdx.x * blockDim.x + threadIdx.x;
    if (gid < E) {
        atomicAdd(&deg[__ldg(ei + E + gid)], 1);
    } else if (gid < E + n) {
        atomicAdd(&cdeg[__ldg(cluster + gid - E)], 1);
    }
}

__global__ __launch_bounds__(512) void scan_block2(
    const int* __restrict__ inN, int* __restrict__ outN, int* __restrict__ sumsN, int n, int nbN,
    const int* __restrict__ inC, int* __restrict__ outC, int* __restrict__ sumsC, int nc)
{
    __shared__ int s[512];
    int tid = threadIdx.x;
    const int* in;  int* out; int* sums; int len; int blk;
    if ((int)blockIdx.x < nbN) { in = inN; out = outN; sums = sumsN; len = n;  blk = blockIdx.x; }
    else                       { in = inC; out = outC; sums = sumsC; len = nc; blk = blockIdx.x - nbN; }
    int i = blk * 512 + tid;
    int v = (i < len) ? in[i] : 0;
    s[tid] = v;
    __syncthreads();
#pragma unroll
    for (int off = 1; off < 512; off <<= 1) {
        int t = (tid >= off) ? s[tid - off] : 0;
        __syncthreads();
        s[tid] += t;
        __syncthreads();
    }
    if (i < len) out[i] = s[tid] - v;
    if (tid == 511) sums[blk] = s[511];
}

__global__ __launch_bounds__(512) void scan_add_fused(
    int* __restrict__ outN, const int* __restrict__ sumsN, int n, int nbN,
    int* __restrict__ outC, const int* __restrict__ sumsC, int nc)
{
    __shared__ int red[16];
    __shared__ int total;
    int tid = threadIdx.x;
    int* out; const int* sums; int len; int blk;
    if ((int)blockIdx.x < nbN) { out = outN; sums = sumsN; len = n;  blk = blockIdx.x; }
    else                       { out = outC; sums = sumsC; len = nc; blk = blockIdx.x - nbN; }
    int p = 0;
    for (int i = tid; i < blk; i += 512) p += sums[i];
#pragma unroll
    for (int off = 16; off >= 1; off >>= 1) p += __shfl_xor_sync(0xffffffffu, p, off);
    if ((tid & 31) == 0) red[tid >> 5] = p;
    __syncthreads();
    if (tid == 0) {
        int t = 0;
#pragma unroll
        for (int i = 0; i < 16; i++) t += red[i];
        total = t;
    }
    __syncthreads();
    int i = blk * 512 + tid;
    if (i < len) out[i] += total;
}

__global__ void scatter_fused(const int* __restrict__ ei, int E,
                              const int* __restrict__ cluster, int n,
                              const int* __restrict__ rowptr, int* __restrict__ cursor,
                              int* __restrict__ esrc,
                              const int* __restrict__ cptr, int* __restrict__ ccur,
                              int* __restrict__ cnodes)
{
    int gid = blockIdx.x * blockDim.x + threadIdx.x;
    if (gid < E) {
        int src = __ldg(ei + gid);
        int tgt = __ldg(ei + E + gid);
        int pos = rowptr[tgt] + atomicAdd(&cursor[tgt], 1);
        esrc[pos] = src;
    } else if (gid < E + n) {
        int i = gid - E;
        int cl = __ldg(cluster + i);
        int pos = cptr[cl] + atomicAdd(&ccur[cl], 1);
        cnodes[pos] = i;
    }
}

// ---------------- fused MLP layer: gemm1+bias+LN+ReLU+gemm2+bias ------------
// Ain [n, C] fp32; W1T [64][C] split bf16, W2T [C][64] split bf16
// Y row stride OS floats; first C cols written here
// A-staging software-pipelined: chunk kc+1 prefetched to regs during MMA of kc
template<int C, int OS>
__global__ __launch_bounds__(256) void fused_mlp(
    const float* __restrict__ Ain,
    const __nv_bfloat16* __restrict__ W1hi, const __nv_bfloat16* __restrict__ W1lo,
    const float* __restrict__ b1, const float* __restrict__ gam,
    const float* __restrict__ bet,
    const __nv_bfloat16* __restrict__ W2hi, const __nv_bfloat16* __restrict__ W2lo,
    const float* __restrict__ b2,
    float* __restrict__ Y, int n)
{
    constexpr int AS  = 72;
    constexpr int WS  = C + 8;
    constexpr int NKC = C / 64;
    constexpr int NG  = C / 64;
    constexpr int W1E = 64 * WS;
    constexpr int AE  = 128 * AS;
    extern __shared__ __align__(16) __nv_bfloat16 sm[];
    __nv_bfloat16* W1s0 = sm;
    __nv_bfloat16* W1s1 = sm + W1E;
    __nv_bfloat16* As0  = sm + 2 * W1E;
    __nv_bfloat16* As1  = As0 + AE;
    __nv_bfloat16* W2s0 = As1 + AE;
    __nv_bfloat16* W2s1 = W2s0 + C * AS;

    const int tid = threadIdx.x, wid = tid >> 5, lane = tid & 31;
    const int g = lane >> 2, q = lane & 3;
    const int r0b = blockIdx.x * 128;

    // load weights (W1 + W2 up front)
    {
        constexpr int VPR = C / 8;
        for (int i = tid; i < 64 * VPR; i += 256) {
            int m = i / VPR, seg = i - m * VPR;
            *(uint4*)&W1s0[m * WS + seg * 8] = __ldg((const uint4*)(W1hi + (size_t)m * C) + seg);
            *(uint4*)&W1s1[m * WS + seg * 8] = __ldg((const uint4*)(W1lo + (size_t)m * C) + seg);
        }
        for (int i = tid; i < C * 8; i += 256) {
            int m = i >> 3, seg = i & 7;
            *(uint4*)&W2s0[m * AS + seg * 8] = __ldg((const uint4*)(W2hi + (size_t)m * 64) + seg);
            *(uint4*)&W2s1[m * AS + seg * 8] = __ldg((const uint4*)(W2lo + (size_t)m * 64) + seg);
        }
    }

    // per-thread ldmatrix address bases
    const int arow = wid * 16 + (lane & 15);
    const int acol = ((lane >> 4) & 1) * 8;
    const uint32_t a_hi = sm_off(As0 + arow * AS + acol);
    const uint32_t a_lo = sm_off(As1 + arow * AS + acol);
    const int brow = (lane & 7) + ((lane >> 4) << 3);
    const int bk8  = ((lane >> 3) & 1) * 8;
    const uint32_t w1h_b = sm_off(W1s0 + brow * WS + bk8);
    const uint32_t w1l_b = sm_off(W1s1 + brow * WS + bk8);
    const uint32_t w2h_b = sm_off(W2s0 + brow * AS + bk8);
    const uint32_t w2l_b = sm_off(W2s1 + brow * AS + bk8);

    // staging map
    const int sm_m = tid >> 5;
    const int sm_e = tid & 31;

    float acc[8][4] = {};

    // stage chunk 0
    {
#pragma unroll
        for (int rpt = 0; rpt < 16; rpt++) {
            int m = sm_m + rpt * 8;
            int r = r0b + m;
            uint32_t h = 0, l = 0;
            if (r < n) {
                float2 v = __ldg((const float2*)Ain + (size_t)r * (C / 2) + sm_e);
                split2(v.x, v.y, h, l);
            }
            *(uint32_t*)&As0[m * AS + 2 * sm_e] = h;
            *(uint32_t*)&As1[m * AS + 2 * sm_e] = l;
        }
    }
    __syncthreads();

    for (int kc = 0; kc < NKC; kc++) {
        // prefetch next chunk to registers (overlaps with MMA below)
        float2 pf[16];
        if (kc + 1 < NKC) {
#pragma unroll
            for (int rpt = 0; rpt < 16; rpt++) {
                int m = sm_m + rpt * 8;
                int r = r0b + m;
                pf[rpt] = (r < n)
                    ? __ldg((const float2*)Ain + (size_t)r * (C / 2) + (kc + 1) * 32 + sm_e)
                    : make_float2(0.f, 0.f);
            }
        }

#pragma unroll
        for (int ks = 0; ks < 4; ks++) {
            const int k0 = ks * 16;
            uint32_t ah[4], al[4];
            ldsm_x4(ah[0], ah[1], ah[2], ah[3], a_hi + k0 * 2);
            ldsm_x4(al[0], al[1], al[2], al[3], a_lo + k0 * 2);
            const int kg = kc * 64 + k0;
#pragma unroll
            for (int jj = 0; jj < 8; jj += 2) {
                uint32_t p0, p1, p2, p3, l0, l1, l2, l3;
                ldsm_x4(p0, p1, p2, p3, w1h_b + (8 * jj * WS + kg) * 2);
                ldsm_x4(l0, l1, l2, l3, w1l_b + (8 * jj * WS + kg) * 2);
                mma16816(acc[jj],     ah, p0, p1);
                mma16816(acc[jj],     ah, l0, l1);
                mma16816(acc[jj],     al, p0, p1);
                mma16816(acc[jj + 1], ah, p2, p3);
                mma16816(acc[jj + 1], ah, l2, l3);
                mma16816(acc[jj + 1], al, p2, p3);
            }
        }

        if (kc + 1 < NKC) {
            __syncthreads();
#pragma unroll
            for (int rpt = 0; rpt < 16; rpt++) {
                int m = sm_m + rpt * 8;
                uint32_t h, l;
                split2(pf[rpt].x, pf[rpt].y, h, l);
                *(uint32_t*)&As0[m * AS + 2 * sm_e] = h;
                *(uint32_t*)&As1[m * AS + 2 * sm_e] = l;
            }
            __syncthreads();
        }
    }

    // ---- gemm1 epilogue: bias + LN (quad shuffle) + ReLU -> H in As --------
    {
        float v0[16], v1[16];
        float s0 = 0.f, q0 = 0.f, s1 = 0.f, q1 = 0.f;
#pragma unroll
        for (int j = 0; j < 8; j++) {
            int c0 = 8*j + 2*q;
            float bx = __ldg(b1 + c0), by = __ldg(b1 + c0 + 1);
            float a = acc[j][0] + bx, b = acc[j][1] + by;
            float c = acc[j][2] + bx, d = acc[j][3] + by;
            v0[2*j] = a; v0[2*j+1] = b; v1[2*j] = c; v1[2*j+1] = d;
            s0 += a + b; q0 += a*a + b*b;
            s1 += c + d; q1 += c*c + d*d;
        }
#pragma unroll
        for (int off = 1; off < 4; off <<= 1) {
            s0 += __shfl_xor_sync(0xffffffffu, s0, off);
            q0 += __shfl_xor_sync(0xffffffffu, q0, off);
            s1 += __shfl_xor_sync(0xffffffffu, s1, off);
            q1 += __shfl_xor_sync(0xffffffffu, q1, off);
        }
        float mu0 = s0 * (1.f/64.f), var0 = q0 * (1.f/64.f) - mu0*mu0;
        float mu1 = s1 * (1.f/64.f), var1 = q1 * (1.f/64.f) - mu1*mu1;
        float rs0 = rsqrtf(var0 + LN_EPS), rs1 = rsqrtf(var1 + LN_EPS);
        __syncthreads();
        int rl0 = wid * 16 + g, rl1 = rl0 + 8;
#pragma unroll
        for (int j = 0; j < 8; j++) {
            int c0 = 8*j + 2*q;
            float ga = __ldg(gam + c0), gb = __ldg(gam + c0 + 1);
            float ba = __ldg(bet + c0), bb = __ldg(bet + c0 + 1);
            float f0 = fmaxf((v0[2*j]   - mu0) * rs0 * ga + ba, 0.f);
            float f1 = fmaxf((v0[2*j+1] - mu0) * rs0 * gb + bb, 0.f);
            float f2 = fmaxf((v1[2*j]   - mu1) * rs1 * ga + ba, 0.f);
            float f3 = fmaxf((v1[2*j+1] - mu1) * rs1 * gb + bb, 0.f);
            uint32_t h, l;
            split2(f0, f1, h, l);
            *(uint32_t*)&As0[rl0 * AS + c0] = h;
            *(uint32_t*)&As1[rl0 * AS + c0] = l;
            split2(f2, f3, h, l);
            *(uint32_t*)&As0[rl1 * AS + c0] = h;
            *(uint32_t*)&As1[rl1 * AS + c0] = l;
        }
    }
    __syncthreads();

    // ---- gemm2: H[128,64] @ W2 -> Y[:, 0:C] --------------------------------
    const int rg0 = r0b + wid * 16 + g;
    const int rg1 = rg0 + 8;

#pragma unroll
    for (int ng = 0; ng < NG; ng++) {
        float acc2[8][4] = {};
#pragma unroll
        for (int ks = 0; ks < 4; ks++) {
            const int k0 = ks * 16;
            uint32_t ah[4], al[4];
            ldsm_x4(ah[0], ah[1], ah[2], ah[3], a_hi + k0 * 2);
            ldsm_x4(al[0], al[1], al[2], al[3], a_lo + k0 * 2);
#pragma unroll
            for (int jj = 0; jj < 8; jj += 2) {
                uint32_t p0, p1, p2, p3, l0, l1, l2, l3;
                ldsm_x4(p0, p1, p2, p3, w2h_b + ((ng * 64 + 8 * jj) * AS + k0) * 2);
                ldsm_x4(l0, l1, l2, l3, w2l_b + ((ng * 64 + 8 * jj) * AS + k0) * 2);
                mma16816(acc2[jj],     ah, p0, p1);
                mma16816(acc2[jj],     ah, l0, l1);
                mma16816(acc2[jj],     al, p0, p1);
                mma16816(acc2[jj + 1], ah, p2, p3);
                mma16816(acc2[jj + 1], ah, l2, l3);
                mma16816(acc2[jj + 1], al, p2, p3);
            }
        }
        if (rg0 < n) {
            float2* orow = (float2*)(Y + (size_t)rg0 * OS) + ng * 32;
#pragma unroll
            for (int j = 0; j < 8; j++) {
                int c0 = 8*j + 2*q;
                orow[4*j + q] = make_float2(acc2[j][0] + __ldg(b2 + ng*64 + c0),
                                            acc2[j][1] + __ldg(b2 + ng*64 + c0 + 1));
            }
        }
        if (rg1 < n) {
            float2* orow = (float2*)(Y + (size_t)rg1 * OS) + ng * 32;
#pragma unroll
            for (int j = 0; j < 8; j++) {
                int c0 = 8*j + 2*q;
                orow[4*j + q] = make_float2(acc2[j][2] + __ldg(b2 + ng*64 + c0),
                                            acc2[j][3] + __ldg(b2 + ng*64 + c0 + 1));
            }
        }
    }
}

// ---------------- CSR gather-max aggregation (fp32, unrolled x4) ------------
template<int C>
__global__ __launch_bounds__(256) void agg_f(
    float* __restrict__ Y, const int* __restrict__ rowptr,
    const int* __restrict__ deg, const int* __restrict__ esrc, int n)
{
    int w = (blockIdx.x * blockDim.x + threadIdx.x) >> 5;
    if (w >= n) return;
    const int lane = threadIdx.x & 31;
    constexpr int EPL = C / 64;
    float2 mx[EPL];
#pragma unroll
    for (int i = 0; i < EPL; i++) mx[i] = make_float2(neg_inf(), neg_inf());
    int d = __ldg(deg + w), base = __ldg(rowptr + w);
    int j = 0;
    for (; j + 3 < d; j += 4) {
        int s0 = __ldg(esrc + base + j);
        int s1 = __ldg(esrc + base + j + 1);
        int s2 = __ldg(esrc + base + j + 2);
        int s3 = __ldg(esrc + base + j + 3);
        const float2* r0 = (const float2*)(Y + (size_t)s0 * (2 * C));
        const float2* r1 = (const float2*)(Y + (size_t)s1 * (2 * C));
        const float2* r2 = (const float2*)(Y + (size_t)s2 * (2 * C));
        const float2* r3 = (const float2*)(Y + (size_t)s3 * (2 * C));
#pragma unroll
        for (int i = 0; i < EPL; i++) {
            float2 v0 = __ldg(r0 + lane + i * 32);
            float2 v1 = __ldg(r1 + lane + i * 32);
            float2 v2 = __ldg(r2 + lane + i * 32);
            float2 v3 = __ldg(r3 + lane + i * 32);
            float ax = fmaxf(fmaxf(v0.x, v1.x), fmaxf(v2.x, v3.x));
            float ay = fmaxf(fmaxf(v0.y, v1.y), fmaxf(v2.y, v3.y));
            mx[i].x = fmaxf(mx[i].x, ax);
            mx[i].y = fmaxf(mx[i].y, ay);
        }
    }
    for (; j < d; j++) {
        int s0 = __ldg(esrc + base + j);
        const float2* r0 = (const float2*)(Y + (size_t)s0 * (2 * C));
#pragma unroll
        for (int i = 0; i < EPL; i++) {
            float2 v0 = __ldg(r0 + lane + i * 32);
            mx[i].x = fmaxf(mx[i].x, v0.x);
            mx[i].y = fmaxf(mx[i].y, v0.y);
        }
    }
    float2* orow = (float2*)(Y + (size_t)w * (2 * C) + C);
#pragma unroll
    for (int i = 0; i < EPL; i++)
        orow[lane + i * 32] = d ? mx[i] : make_float2(0.f, 0.f);
}

// ---------------- fused layer-2 agg + cluster max-pool (edge unroll x4) -----
__global__ __launch_bounds__(128) void pool_agg(
    const float* __restrict__ Y,
    const int* __restrict__ cptr, const int* __restrict__ cdeg,
    const int* __restrict__ cnodes,
    const int* __restrict__ rowptr, const int* __restrict__ deg,
    const int* __restrict__ esrc,
    float* __restrict__ out)
{
    int cl = blockIdx.x, t = threadIdx.x;
    int cd = __ldg(cdeg + cl), cbase = __ldg(cptr + cl);
    float2 m0 = make_float2(neg_inf(), neg_inf());
    float2 m1 = m0;
    bool zerodeg = false;
    for (int j = 0; j < cd; j++) {
        int nd = __ldg(cnodes + cbase + j);
        const float2* row = (const float2*)(Y + (size_t)nd * 256);
        float2 v = __ldg(row + t);
        m0.x = fmaxf(m0.x, v.x); m0.y = fmaxf(m0.y, v.y);
        int d = __ldg(deg + nd), eb = __ldg(rowptr + nd);
        if (d == 0) zerodeg = true;
        int e = 0;
        for (; e + 3 < d; e += 4) {
            int s0 = __ldg(esrc + eb + e);
            int s1 = __ldg(esrc + eb + e + 1);
            int s2 = __ldg(esrc + eb + e + 2);
            int s3 = __ldg(esrc + eb + e + 3);
            float2 w0 = __ldg((const float2*)(Y + (size_t)s0 * 256) + t);
            float2 w1 = __ldg((const float2*)(Y + (size_t)s1 * 256) + t);
            float2 w2 = __ldg((const float2*)(Y + (size_t)s2 * 256) + t);
            float2 w3 = __ldg((const float2*)(Y + (size_t)s3 * 256) + t);
            m1.x = fmaxf(m1.x, fmaxf(fmaxf(w0.x, w1.x), fmaxf(w2.x, w3.x)));
            m1.y = fmaxf(m1.y, fmaxf(fmaxf(w0.y, w1.y), fmaxf(w2.y, w3.y)));
        }
        for (; e < d; e++) {
            int s0 = __ldg(esrc + eb + e);
            float2 w0 = __ldg((const float2*)(Y + (size_t)s0 * 256) + t);
            m1.x = fmaxf(m1.x, w0.x);
            m1.y = fmaxf(m1.y, w0.y);
        }
    }
    if (cd == 0) {
        m0 = make_float2(0.f, 0.f);
        m1 = m0;
    } else if (zerodeg) {
        m1.x = fmaxf(m1.x, 0.f);
        m1.y = fmaxf(m1.y, 0.f);
    }
    float2* orow = (float2*)(out + (size_t)cl * 512);
    orow[t] = m0;
    orow[t + 128] = m1;
}

// ---------------- column L2 normalize ---------------------------------------
__global__ __launch_bounds__(512) void colsq_kernel(const float* __restrict__ out,
                                                    float* __restrict__ colsq, int nc)
{
    const int ROWS = 50;
    int c  = threadIdx.x;
    int r0 = blockIdx.x * ROWS;
    int r1 = min(r0 + ROWS, nc);
    float s = 0.f;
    for (int r = r0; r < r1; r++) {
        float f = out[(size_t)r * 512 + c];
        s += f * f;
    }
    atomicAdd(colsq + c, s);
}

__global__ void scale_kernel(float* __restrict__ out, const float* __restrict__ colsq, int nc)
{
    int gid = blockIdx.x * blockDim.x + threadIdx.x;
    if (gid >= nc * 128) return;
    int c4 = gid & 127;
    float4 v = *(float4*)(out + (size_t)gid * 4);
    float4 s = *(const float4*)(colsq + c4 * 4);
    v.x *= rsqrtf(s.x); v.y *= rsqrtf(s.y);
    v.z *= rsqrtf(s.z); v.w *= rsqrtf(s.w);
    *(float4*)(out + (size_t)gid * 4) = v;
}

// ---------------- launch ----------------------------------------------------
extern "C" void kernel_launch(void* const* d_in, const int* in_sizes, int n_in,
                              void* d_out, int out_size)
{
    const float* x       = (const float*)d_in[0];
    const int*   ei      = (const int*)d_in[1];
    const int*   cluster = (const int*)d_in[2];
    const int N  = in_sizes[0] / 64;
    const int E  = in_sizes[1] / 2;
    const int NC = out_size / 512;
    float* out = (float*)d_out;

    float *y0, *y1, *y2, *colsq;
    __nv_bfloat16 *w1h[3], *w1l[3], *w2h[3], *w2l[3];
    int *deg, *rowptr, *cursor, *esrc, *cdeg, *cptr, *ccur, *cnodes, *bsumsN, *bsumsC;
    cudaGetSymbolAddress((void**)&y0, g_y0);
    cudaGetSymbolAddress((void**)&y1, g_y1);
    cudaGetSymbolAddress((void**)&y2, g_y2);
    cudaGetSymbolAddress((void**)&w1h[0], g_w1thi0); cudaGetSymbolAddress((void**)&w1l[0], g_w1tlo0);
    cudaGetSymbolAddress((void**)&w1h[1], g_w1thi1); cudaGetSymbolAddress((void**)&w1l[1], g_w1tlo1);
    cudaGetSymbolAddress((void**)&w1h[2], g_w1thi2); cudaGetSymbolAddress((void**)&w1l[2], g_w1tlo2);
    cudaGetSymbolAddress((void**)&w2h[0], g_w2thi0); cudaGetSymbolAddress((void**)&w2l[0], g_w2tlo0);
    cudaGetSymbolAddress((void**)&w2h[1], g_w2thi1); cudaGetSymbolAddress((void**)&w2l[1], g_w2tlo1);
    cudaGetSymbolAddress((void**)&w2h[2], g_w2thi2); cudaGetSymbolAddress((void**)&w2l[2], g_w2tlo2);
    cudaGetSymbolAddress((void**)&colsq,  g_colsq);
    cudaGetSymbolAddress((void**)&deg,    g_deg);
    cudaGetSymbolAddress((void**)&rowptr, g_rowptr);
    cudaGetSymbolAddress((void**)&cursor, g_cursor);
    cudaGetSymbolAddress((void**)&esrc,   g_esrc);
    cudaGetSymbolAddress((void**)&cdeg,   g_cdeg);
    cudaGetSymbolAddress((void**)&cptr,   g_cptr);
    cudaGetSymbolAddress((void**)&ccur,   g_ccur);
    cudaGetSymbolAddress((void**)&cnodes, g_cnodes);
    cudaGetSymbolAddress((void**)&bsumsN, g_bsumsN);
    cudaGetSymbolAddress((void**)&bsumsC, g_bsumsC);

    const int SM64  = 2 * (64*72  + 128*72 + 64*72 ) * 2;   //  73728
    const int SM128 = 2 * (64*136 + 128*72 + 128*72) * 2;   // 108544
    const int SM256 = 2 * (64*264 + 128*72 + 256*72) * 2;   // 178176
    cudaFuncSetAttribute((const void*)fused_mlp<64, 128>,  cudaFuncAttributeMaxDynamicSharedMemorySize, SM64);
    cudaFuncSetAttribute((const void*)fused_mlp<128, 256>, cudaFuncAttributeMaxDynamicSharedMemorySize, SM128);
    cudaFuncSetAttribute((const void*)fused_mlp<256, 256>, cudaFuncAttributeMaxDynamicSharedMemorySize, SM256);

    const int GRID = (N + 127) / 128;
    const int nbN = (N + 511) / 512;
    const int nbC = (NC + 511) / 512;

    // ---- init: zero counters + weight conversion (1 launch) ----
    {
        WConv a;
        int off = 0;
        const int CINs[3] = {64, 128, 256};
        for (int i = 0; i < 3; i++) {
            int c = CINs[i];
            a.in[2*i]   = (const float*)d_in[3 + 6*i];
            a.hi[2*i]   = w1h[i]; a.lo[2*i] = w1l[i];
            a.K[2*i]    = c;  a.M[2*i] = 64;
            a.off[2*i]  = off; off += c * 64;
            a.in[2*i+1] = (const float*)d_in[3 + 6*i + 4];
            a.hi[2*i+1] = w2h[i]; a.lo[2*i+1] = w2l[i];
            a.K[2*i+1]  = 64; a.M[2*i+1] = c;
            a.off[2*i+1] = off; off += 64 * c;
        }
        a.off[6] = off;
        int span = N > off ? N : off;
        init_misc<<<(span + 255) / 256, 256>>>(a, deg, cursor, cdeg, ccur, colsq, N, NC);
    }

    // ---- CSR build (4 launches) ----
    hist_fused<<<(E + N + 255) / 256, 256>>>(ei, E, cluster, N, deg, cdeg);
    scan_block2<<<nbN + nbC, 512>>>(deg, rowptr, bsumsN, N, nbN, cdeg, cptr, bsumsC, NC);
    scan_add_fused<<<nbN + nbC, 512>>>(rowptr, bsumsN, N, nbN, cptr, bsumsC, NC);
    scatter_fused<<<(E + N + 255) / 256, 256>>>(ei, E, cluster, N, rowptr, cursor, esrc,
                                                cptr, ccur, cnodes);

    // ---- layers ----
    fused_mlp<64, 128><<<GRID, 256, SM64>>>(
        x, w1h[0], w1l[0], (const float*)d_in[4], (const float*)d_in[5],
        (const float*)d_in[6], w2h[0], w2l[0], (const float*)d_in[8], y0, N);
    agg_f<64><<<(N + 7) / 8, 256>>>(y0, rowptr, deg, esrc, N);

    fused_mlp<128, 256><<<GRID, 256, SM128>>>(
        y0, w1h[1], w1l[1], (const float*)d_in[10], (const float*)d_in[11],
        (const float*)d_in[12], w2h[1], w2l[1], (const float*)d_in[14], y1, N);
    agg_f<128><<<(N + 7) / 8, 256>>>(y1, rowptr, deg, esrc, N);

    fused_mlp<256, 256><<<GRID, 256, SM256>>>(
        y1, w1h[2], w1l[2], (const float*)d_in[16], (const float*)d_in[17],
        (const float*)d_in[18], w2h[2], w2l[2], (const float*)d_in[20], y2, N);

    // ---- fused layer-2 agg + cluster max-pool + column L2 normalize ----
    pool_agg<<<NC, 128>>>(y2, cptr, cdeg, cnodes, rowptr, deg, esrc, out);
    colsq_kernel<<<(NC + 49) / 50, 512>>>(out, colsq, NC);
    scale_kernel<<<(NC * 128 + 255) / 256, 256>>>(out, colsq, NC);
}

// round 15
// speedup vs baseline: 1.4423x; 1.0029x over previous
#include <cuda_runtime.h>
#include <cuda_bf16.h>
#include <cstdint>

#define LN_EPS 1e-5f

// ---------------- scratch (device globals: allocation-free) ----------------
__device__ __align__(128) float g_y0[100000 * 128];
__device__ __align__(128) float g_y1[100000 * 256];
__device__ __align__(128) float g_y2[100000 * 256];   // layer2 GEMM out only
__device__ __align__(128) __nv_bfloat16 g_w1thi0[64*64],  g_w1tlo0[64*64];
__device__ __align__(128) __nv_bfloat16 g_w1thi1[64*128], g_w1tlo1[64*128];
__device__ __align__(128) __nv_bfloat16 g_w1thi2[64*256], g_w1tlo2[64*256];
__device__ __align__(128) __nv_bfloat16 g_w2thi0[64*64],  g_w2tlo0[64*64];
__device__ __align__(128) __nv_bfloat16 g_w2thi1[128*64], g_w2tlo1[128*64];
__device__ __align__(128) __nv_bfloat16 g_w2thi2[256*64], g_w2tlo2[256*64];
__device__ float g_colsq[512];

// CSR scratch
__device__ int g_deg[100000];
__device__ int g_rowptr[100000];
__device__ int g_cursor[100000];
__device__ int g_esrc[800000];
__device__ int g_cdeg[10000];
__device__ int g_cptr[10000];
__device__ int g_ccur[10000];
__device__ int g_cnodes[100000];
__device__ int g_bsumsN[512];
__device__ int g_bsumsC[512];

__device__ __forceinline__ float neg_inf() { return __int_as_float(0xff800000); }

__device__ __forceinline__ void split2(float a, float b, uint32_t& hi, uint32_t& lo) {
    __nv_bfloat16 ah = __float2bfloat16_rn(a);
    __nv_bfloat16 bh = __float2bfloat16_rn(b);
    __nv_bfloat16 al = __float2bfloat16_rn(a - __bfloat162float(ah));
    __nv_bfloat16 bl = __float2bfloat16_rn(b - __bfloat162float(bh));
    __nv_bfloat162 h = __halves2bfloat162(ah, bh);
    __nv_bfloat162 l = __halves2bfloat162(al, bl);
    hi = *reinterpret_cast<uint32_t*>(&h);
    lo = *reinterpret_cast<uint32_t*>(&l);
}

__device__ __forceinline__ void mma16816(float* c, const uint32_t* a,
                                         uint32_t b0, uint32_t b1) {
    asm volatile(
        "mma.sync.aligned.m16n8k16.row.col.f32.bf16.bf16.f32 "
        "{%0,%1,%2,%3}, {%4,%5,%6,%7}, {%8,%9}, {%0,%1,%2,%3};"
        : "+f"(c[0]), "+f"(c[1]), "+f"(c[2]), "+f"(c[3])
        : "r"(a[0]), "r"(a[1]), "r"(a[2]), "r"(a[3]), "r"(b0), "r"(b1));
}

__device__ __forceinline__ uint32_t sm_off(const void* p) {
    uint32_t a;
    asm("{ .reg .u64 t; cvta.to.shared.u64 t, %1; cvt.u32.u64 %0, t; }" : "=r"(a) : "l"(p));
    return a;
}

__device__ __forceinline__ void ldsm_x4(uint32_t& r0, uint32_t& r1,
                                        uint32_t& r2, uint32_t& r3, uint32_t addr) {
    asm volatile("ldmatrix.sync.aligned.m8n8.x4.shared.b16 {%0,%1,%2,%3}, [%4];"
                 : "=r"(r0), "=r"(r1), "=r"(r2), "=r"(r3) : "r"(addr));
}

// ---------------- init kernels ----------------------------------------------
struct WConv {
    const float* in[6];
    __nv_bfloat16* hi[6];
    __nv_bfloat16* lo[6];
    int K[6], M[6];
    int off[7];
};

__global__ void conv_weights(WConv a)
{
    int gid = blockIdx.x * blockDim.x + threadIdx.x;
    if (gid >= a.off[6]) return;
    int s = 0;
#pragma unroll
    for (int i = 1; i < 6; i++) if (gid >= a.off[i]) s = i;
    int local = gid - a.off[s];
    int M = a.M[s], K = a.K[s];
    int k = local / M, m = local - k * M;
    float v = __ldg(a.in[s] + local);
    __nv_bfloat16 h = __float2bfloat16_rn(v);
    a.hi[s][m * K + k] = h;
    a.lo[s][m * K + k] = __float2bfloat16_rn(v - __bfloat162float(h));
}

__global__ void init_csr(int* __restrict__ deg, int* __restrict__ cursor,
                         int* __restrict__ cdeg, int* __restrict__ ccur,
                         float* __restrict__ colsq, int n, int nc)
{
    int gid = blockIdx.x * blockDim.x + threadIdx.x;
    if (gid < n) { deg[gid] = 0; cursor[gid] = 0; }
    if (gid < nc) { cdeg[gid] = 0; ccur[gid] = 0; }
    if (gid < 512) colsq[gid] = 0.f;
}

// ---------------- CSR build --------------------------------------------------
__global__ void hist_fused(const int* __restrict__ ei, int E,
                           const int* __restrict__ cluster, int n,
                           int* __restrict__ deg, int* __restrict__ cdeg)
{
    int gid = blockIdx.x * blockDim.x + threadIdx.x;
    if (gid < E) {
        atomicAdd(&deg[__ldg(ei + E + gid)], 1);
    } else if (gid < E + n) {
        atomicAdd(&cdeg[__ldg(cluster + gid - E)], 1);
    }
}

__global__ __launch_bounds__(512) void scan_block2(
    const int* __restrict__ inN, int* __restrict__ outN, int* __restrict__ sumsN, int n, int nbN,
    const int* __restrict__ inC, int* __restrict__ outC, int* __restrict__ sumsC, int nc)
{
    __shared__ int s[512];
    int tid = threadIdx.x;
    const int* in;  int* out; int* sums; int len; int blk;
    if ((int)blockIdx.x < nbN) { in = inN; out = outN; sums = sumsN; len = n;  blk = blockIdx.x; }
    else                       { in = inC; out = outC; sums = sumsC; len = nc; blk = blockIdx.x - nbN; }
    int i = blk * 512 + tid;
    int v = (i < len) ? in[i] : 0;
    s[tid] = v;
    __syncthreads();
#pragma unroll
    for (int off = 1; off < 512; off <<= 1) {
        int t = (tid >= off) ? s[tid - off] : 0;
        __syncthreads();
        s[tid] += t;
        __syncthreads();
    }
    if (i < len) out[i] = s[tid] - v;
    if (tid == 511) sums[blk] = s[511];
}

__global__ __launch_bounds__(512) void scan_add_fused(
    int* __restrict__ outN, const int* __restrict__ sumsN, int n, int nbN,
    int* __restrict__ outC, const int* __restrict__ sumsC, int nc)
{
    __shared__ int red[16];
    __shared__ int total;
    int tid = threadIdx.x;
    int* out; const int* sums; int len; int blk;
    if ((int)blockIdx.x < nbN) { out = outN; sums = sumsN; len = n;  blk = blockIdx.x; }
    else                       { out = outC; sums = sumsC; len = nc; blk = blockIdx.x - nbN; }
    int p = 0;
    for (int i = tid; i < blk; i += 512) p += sums[i];
#pragma unroll
    for (int off = 16; off >= 1; off >>= 1) p += __shfl_xor_sync(0xffffffffu, p, off);
    if ((tid & 31) == 0) red[tid >> 5] = p;
    __syncthreads();
    if (tid == 0) {
        int t = 0;
#pragma unroll
        for (int i = 0; i < 16; i++) t += red[i];
        total = t;
    }
    __syncthreads();
    int i = blk * 512 + tid;
    if (i < len) out[i] += total;
}

__global__ void scatter_fused(const int* __restrict__ ei, int E,
                              const int* __restrict__ cluster, int n,
                              const int* __restrict__ rowptr, int* __restrict__ cursor,
                              int* __restrict__ esrc,
                              const int* __restrict__ cptr, int* __restrict__ ccur,
                              int* __restrict__ cnodes)
{
    int gid = blockIdx.x * blockDim.x + threadIdx.x;
    if (gid < E) {
        int src = __ldg(ei + gid);
        int tgt = __ldg(ei + E + gid);
        int pos = rowptr[tgt] + atomicAdd(&cursor[tgt], 1);
        esrc[pos] = src;
    } else if (gid < E + n) {
        int i = gid - E;
        int cl = __ldg(cluster + i);
        int pos = cptr[cl] + atomicAdd(&ccur[cl], 1);
        cnodes[pos] = i;
    }
}

// ---------------- fused MLP layer: gemm1+bias+LN+ReLU+gemm2+bias ------------
template<int C, int OS>
__global__ __launch_bounds__(256) void fused_mlp(
    const float* __restrict__ Ain,
    const __nv_bfloat16* __restrict__ W1hi, const __nv_bfloat16* __restrict__ W1lo,
    const float* __restrict__ b1, const float* __restrict__ gam,
    const float* __restrict__ bet,
    const __nv_bfloat16* __restrict__ W2hi, const __nv_bfloat16* __restrict__ W2lo,
    const float* __restrict__ b2,
    float* __restrict__ Y, int n)
{
    constexpr int AS  = 72;
    constexpr int WS  = C + 8;
    constexpr int NKC = C / 64;
    constexpr int NG  = C / 64;
    constexpr int W1E = 64 * WS;
    constexpr int AE  = 128 * AS;
    extern __shared__ __align__(16) __nv_bfloat16 sm[];
    __nv_bfloat16* W1s0 = sm;
    __nv_bfloat16* W1s1 = sm + W1E;
    __nv_bfloat16* As0  = sm + 2 * W1E;
    __nv_bfloat16* As1  = As0 + AE;
    __nv_bfloat16* W2s0 = As1 + AE;
    __nv_bfloat16* W2s1 = W2s0 + C * AS;

    const int tid = threadIdx.x, wid = tid >> 5, lane = tid & 31;
    const int g = lane >> 2, q = lane & 3;
    const int r0b = blockIdx.x * 128;

    {
        constexpr int VPR = C / 8;
        for (int i = tid; i < 64 * VPR; i += 256) {
            int m = i / VPR, seg = i - m * VPR;
            *(uint4*)&W1s0[m * WS + seg * 8] = __ldg((const uint4*)(W1hi + (size_t)m * C) + seg);
            *(uint4*)&W1s1[m * WS + seg * 8] = __ldg((const uint4*)(W1lo + (size_t)m * C) + seg);
        }
        for (int i = tid; i < C * 8; i += 256) {
            int m = i >> 3, seg = i & 7;
            *(uint4*)&W2s0[m * AS + seg * 8] = __ldg((const uint4*)(W2hi + (size_t)m * 64) + seg);
            *(uint4*)&W2s1[m * AS + seg * 8] = __ldg((const uint4*)(W2lo + (size_t)m * 64) + seg);
        }
    }

    const int arow = wid * 16 + (lane & 15);
    const int acol = ((lane >> 4) & 1) * 8;
    const uint32_t a_hi = sm_off(As0 + arow * AS + acol);
    const uint32_t a_lo = sm_off(As1 + arow * AS + acol);
    const int brow = (lane & 7) + ((lane >> 4) << 3);
    const int bk8  = ((lane >> 3) & 1) * 8;
    const uint32_t w1h_b = sm_off(W1s0 + brow * WS + bk8);
    const uint32_t w1l_b = sm_off(W1s1 + brow * WS + bk8);
    const uint32_t w2h_b = sm_off(W2s0 + brow * AS + bk8);
    const uint32_t w2l_b = sm_off(W2s1 + brow * AS + bk8);

    const int sm_m = tid >> 5;
    const int sm_e = tid & 31;

    float acc[8][4] = {};

    // stage chunk 0
    {
#pragma unroll
        for (int rpt = 0; rpt < 16; rpt++) {
            int m = sm_m + rpt * 8;
            int r = r0b + m;
            uint32_t h = 0, l = 0;
            if (r < n) {
                float2 v = __ldg((const float2*)Ain + (size_t)r * (C / 2) + sm_e);
                split2(v.x, v.y, h, l);
            }
            *(uint32_t*)&As0[m * AS + 2 * sm_e] = h;
            *(uint32_t*)&As1[m * AS + 2 * sm_e] = l;
        }
    }
    __syncthreads();

    for (int kc = 0; kc < NKC; kc++) {
        float2 pf[16];
        if (kc + 1 < NKC) {
#pragma unroll
            for (int rpt = 0; rpt < 16; rpt++) {
                int m = sm_m + rpt * 8;
                int r = r0b + m;
                pf[rpt] = (r < n)
                    ? __ldg((const float2*)Ain + (size_t)r * (C / 2) + (kc + 1) * 32 + sm_e)
                    : make_float2(0.f, 0.f);
            }
        }

#pragma unroll
        for (int ks = 0; ks < 4; ks++) {
            const int k0 = ks * 16;
            uint32_t ah[4], al[4];
            ldsm_x4(ah[0], ah[1], ah[2], ah[3], a_hi + k0 * 2);
            ldsm_x4(al[0], al[1], al[2], al[3], a_lo + k0 * 2);
            const int kg = kc * 64 + k0;
#pragma unroll
            for (int jj = 0; jj < 8; jj += 2) {
                uint32_t p0, p1, p2, p3, l0, l1, l2, l3;
                ldsm_x4(p0, p1, p2, p3, w1h_b + (8 * jj * WS + kg) * 2);
                ldsm_x4(l0, l1, l2, l3, w1l_b + (8 * jj * WS + kg) * 2);
                mma16816(acc[jj],     ah, p0, p1);
                mma16816(acc[jj],     ah, l0, l1);
                mma16816(acc[jj],     al, p0, p1);
                mma16816(acc[jj + 1], ah, p2, p3);
                mma16816(acc[jj + 1], ah, l2, l3);
                mma16816(acc[jj + 1], al, p2, p3);
            }
        }

        if (kc + 1 < NKC) {
            __syncthreads();
#pragma unroll
            for (int rpt = 0; rpt < 16; rpt++) {
                int m = sm_m + rpt * 8;
                uint32_t h, l;
                split2(pf[rpt].x, pf[rpt].y, h, l);
                *(uint32_t*)&As0[m * AS + 2 * sm_e] = h;
                *(uint32_t*)&As1[m * AS + 2 * sm_e] = l;
            }
            __syncthreads();
        }
    }

    // ---- gemm1 epilogue: bias + LN (quad shuffle) + ReLU -> H in As --------
    {
        float v0[16], v1[16];
        float s0 = 0.f, q0 = 0.f, s1 = 0.f, q1 = 0.f;
#pragma unroll
        for (int j = 0; j < 8; j++) {
            int c0 = 8*j + 2*q;
            float bx = __ldg(b1 + c0), by = __ldg(b1 + c0 + 1);
            float a = acc[j][0] + bx, b = acc[j][1] + by;
            float c = acc[j][2] + bx, d = acc[j][3] + by;
            v0[2*j] = a; v0[2*j+1] = b; v1[2*j] = c; v1[2*j+1] = d;
            s0 += a + b; q0 += a*a + b*b;
            s1 += c + d; q1 += c*c + d*d;
        }
#pragma unroll
        for (int off = 1; off < 4; off <<= 1) {
            s0 += __shfl_xor_sync(0xffffffffu, s0, off);
            q0 += __shfl_xor_sync(0xffffffffu, q0, off);
            s1 += __shfl_xor_sync(0xffffffffu, s1, off);
            q1 += __shfl_xor_sync(0xffffffffu, q1, off);
        }
        float mu0 = s0 * (1.f/64.f), var0 = q0 * (1.f/64.f) - mu0*mu0;
        float mu1 = s1 * (1.f/64.f), var1 = q1 * (1.f/64.f) - mu1*mu1;
        float rs0 = rsqrtf(var0 + LN_EPS), rs1 = rsqrtf(var1 + LN_EPS);
        __syncthreads();
        int rl0 = wid * 16 + g, rl1 = rl0 + 8;
#pragma unroll
        for (int j = 0; j < 8; j++) {
            int c0 = 8*j + 2*q;
            float ga = __ldg(gam + c0), gb = __ldg(gam + c0 + 1);
            float ba = __ldg(bet + c0), bb = __ldg(bet + c0 + 1);
            float f0 = fmaxf((v0[2*j]   - mu0) * rs0 * ga + ba, 0.f);
            float f1 = fmaxf((v0[2*j+1] - mu0) * rs0 * gb + bb, 0.f);
            float f2 = fmaxf((v1[2*j]   - mu1) * rs1 * ga + ba, 0.f);
            float f3 = fmaxf((v1[2*j+1] - mu1) * rs1 * gb + bb, 0.f);
            uint32_t h, l;
            split2(f0, f1, h, l);
            *(uint32_t*)&As0[rl0 * AS + c0] = h;
            *(uint32_t*)&As1[rl0 * AS + c0] = l;
            split2(f2, f3, h, l);
            *(uint32_t*)&As0[rl1 * AS + c0] = h;
            *(uint32_t*)&As1[rl1 * AS + c0] = l;
        }
    }
    __syncthreads();

    // ---- gemm2: H[128,64] @ W2 -> Y[:, 0:C] --------------------------------
    const int rg0 = r0b + wid * 16 + g;
    const int rg1 = rg0 + 8;

#pragma unroll
    for (int ng = 0; ng < NG; ng++) {
        float acc2[8][4] = {};
#pragma unroll
        for (int ks = 0; ks < 4; ks++) {
            const int k0 = ks * 16;
            uint32_t ah[4], al[4];
            ldsm_x4(ah[0], ah[1], ah[2], ah[3], a_hi + k0 * 2);
            ldsm_x4(al[0], al[1], al[2], al[3], a_lo + k0 * 2);
#pragma unroll
            for (int jj = 0; jj < 8; jj += 2) {
                uint32_t p0, p1, p2, p3, l0, l1, l2, l3;
                ldsm_x4(p0, p1, p2, p3, w2h_b + ((ng * 64 + 8 * jj) * AS + k0) * 2);
                ldsm_x4(l0, l1, l2, l3, w2l_b + ((ng * 64 + 8 * jj) * AS + k0) * 2);
                mma16816(acc2[jj],     ah, p0, p1);
                mma16816(acc2[jj],     ah, l0, l1);
                mma16816(acc2[jj],     al, p0, p1);
                mma16816(acc2[jj + 1], ah, p2, p3);
                mma16816(acc2[jj + 1], ah, l2, l3);
                mma16816(acc2[jj + 1], al, p2, p3);
            }
        }
        if (rg0 < n) {
            float2* orow = (float2*)(Y + (size_t)rg0 * OS) + ng * 32;
#pragma unroll
            for (int j = 0; j < 8; j++) {
                int c0 = 8*j + 2*q;
                orow[4*j + q] = make_float2(acc2[j][0] + __ldg(b2 + ng*64 + c0),
                                            acc2[j][1] + __ldg(b2 + ng*64 + c0 + 1));
            }
        }
        if (rg1 < n) {
            float2* orow = (float2*)(Y + (size_t)rg1 * OS) + ng * 32;
#pragma unroll
            for (int j = 0; j < 8; j++) {
                int c0 = 8*j + 2*q;
                orow[4*j + q] = make_float2(acc2[j][2] + __ldg(b2 + ng*64 + c0),
                                            acc2[j][3] + __ldg(b2 + ng*64 + c0 + 1));
            }
        }
    }
}

// ---------------- CSR gather-max aggregation (fp32, unrolled x4) ------------
template<int C>
__global__ __launch_bounds__(256) void agg_f(
    float* __restrict__ Y, const int* __restrict__ rowptr,
    const int* __restrict__ deg, const int* __restrict__ esrc, int n)
{
    int w = (blockIdx.x * blockDim.x + threadIdx.x) >> 5;
    if (w >= n) return;
    const int lane = threadIdx.x & 31;
    constexpr int EPL = C / 64;
    float2 mx[EPL];
#pragma unroll
    for (int i = 0; i < EPL; i++) mx[i] = make_float2(neg_inf(), neg_inf());
    int d = __ldg(deg + w), base = __ldg(rowptr + w);
    int j = 0;
    for (; j + 3 < d; j += 4) {
        int s0 = __ldg(esrc + base + j);
        int s1 = __ldg(esrc + base + j + 1);
        int s2 = __ldg(esrc + base + j + 2);
        int s3 = __ldg(esrc + base + j + 3);
        const float2* r0 = (const float2*)(Y + (size_t)s0 * (2 * C));
        const float2* r1 = (const float2*)(Y + (size_t)s1 * (2 * C));
        const float2* r2 = (const float2*)(Y + (size_t)s2 * (2 * C));
        const float2* r3 = (const float2*)(Y + (size_t)s3 * (2 * C));
#pragma unroll
        for (int i = 0; i < EPL; i++) {
            float2 v0 = __ldg(r0 + lane + i * 32);
            float2 v1 = __ldg(r1 + lane + i * 32);
            float2 v2 = __ldg(r2 + lane + i * 32);
            float2 v3 = __ldg(r3 + lane + i * 32);
            float ax = fmaxf(fmaxf(v0.x, v1.x), fmaxf(v2.x, v3.x));
            float ay = fmaxf(fmaxf(v0.y, v1.y), fmaxf(v2.y, v3.y));
            mx[i].x = fmaxf(mx[i].x, ax);
            mx[i].y = fmaxf(mx[i].y, ay);
        }
    }
    for (; j < d; j++) {
        int s0 = __ldg(esrc + base + j);
        const float2* r0 = (const float2*)(Y + (size_t)s0 * (2 * C));
#pragma unroll
        for (int i = 0; i < EPL; i++) {
            float2 v0 = __ldg(r0 + lane + i * 32);
            mx[i].x = fmaxf(mx[i].x, v0.x);
            mx[i].y = fmaxf(mx[i].y, v0.y);
        }
    }
    float2* orow = (float2*)(Y + (size_t)w * (2 * C) + C);
#pragma unroll
    for (int i = 0; i < EPL; i++)
        orow[lane + i * 32] = d ? mx[i] : make_float2(0.f, 0.f);
}

// ---------------- fused layer-2 agg + cluster max-pool ----------------------
__global__ __launch_bounds__(128) void pool_agg(
    const float* __restrict__ Y,
    const int* __restrict__ cptr, const int* __restrict__ cdeg,
    const int* __restrict__ cnodes,
    const int* __restrict__ rowptr, const int* __restrict__ deg,
    const int* __restrict__ esrc,
    float* __restrict__ out)
{
    int cl = blockIdx.x, t = threadIdx.x;
    int cd = __ldg(cdeg + cl), cbase = __ldg(cptr + cl);
    float2 m0 = make_float2(neg_inf(), neg_inf());
    float2 m1 = m0;
    bool zerodeg = false;
    for (int j = 0; j < cd; j++) {
        int nd = __ldg(cnodes + cbase + j);
        const float2* row = (const float2*)(Y + (size_t)nd * 256);
        float2 v = __ldg(row + t);
        m0.x = fmaxf(m0.x, v.x); m0.y = fmaxf(m0.y, v.y);
        int d = __ldg(deg + nd), eb = __ldg(rowptr + nd);
        if (d == 0) zerodeg = true;
        int e = 0;
        for (; e + 3 < d; e += 4) {
            int s0 = __ldg(esrc + eb + e);
            int s1 = __ldg(esrc + eb + e + 1);
            int s2 = __ldg(esrc + eb + e + 2);
            int s3 = __ldg(esrc + eb + e + 3);
            float2 w0 = __ldg((const float2*)(Y + (size_t)s0 * 256) + t);
            float2 w1 = __ldg((const float2*)(Y + (size_t)s1 * 256) + t);
            float2 w2 = __ldg((const float2*)(Y + (size_t)s2 * 256) + t);
            float2 w3 = __ldg((const float2*)(Y + (size_t)s3 * 256) + t);
            m1.x = fmaxf(m1.x, fmaxf(fmaxf(w0.x, w1.x), fmaxf(w2.x, w3.x)));
            m1.y = fmaxf(m1.y, fmaxf(fmaxf(w0.y, w1.y), fmaxf(w2.y, w3.y)));
        }
        for (; e < d; e++) {
            int s0 = __ldg(esrc + eb + e);
            float2 w0 = __ldg((const float2*)(Y + (size_t)s0 * 256) + t);
            m1.x = fmaxf(m1.x, w0.x);
            m1.y = fmaxf(m1.y, w0.y);
        }
    }
    if (cd == 0) {
        m0 = make_float2(0.f, 0.f);
        m1 = m0;
    } else if (zerodeg) {
        m1.x = fmaxf(m1.x, 0.f);
        m1.y = fmaxf(m1.y, 0.f);
    }
    float2* orow = (float2*)(out + (size_t)cl * 512);
    orow[t] = m0;
    orow[t + 128] = m1;
}

// ---------------- column L2 normalize ---------------------------------------
__global__ __launch_bounds__(512) void colsq_kernel(const float* __restrict__ out,
                                                    float* __restrict__ colsq, int nc)
{
    const int ROWS = 50;
    int c  = threadIdx.x;
    int r0 = blockIdx.x * ROWS;
    int r1 = min(r0 + ROWS, nc);
    float s = 0.f;
    for (int r = r0; r < r1; r++) {
        float f = out[(size_t)r * 512 + c];
        s += f * f;
    }
    atomicAdd(colsq + c, s);
}

__global__ void scale_kernel(float* __restrict__ out, const float* __restrict__ colsq, int nc)
{
    int gid = blockIdx.x * blockDim.x + threadIdx.x;
    if (gid >= nc * 128) return;
    int c4 = gid & 127;
    float4 v = *(float4*)(out + (size_t)gid * 4);
    float4 s = *(const float4*)(colsq + c4 * 4);
    v.x *= rsqrtf(s.x); v.y *= rsqrtf(s.y);
    v.z *= rsqrtf(s.z); v.w *= rsqrtf(s.w);
    *(float4*)(out + (size_t)gid * 4) = v;
}

// ---------------- launch ----------------------------------------------------
extern "C" void kernel_launch(void* const* d_in, const int* in_sizes, int n_in,
                              void* d_out, int out_size)
{
    const float* x       = (const float*)d_in[0];
    const int*   ei      = (const int*)d_in[1];
    const int*   cluster = (const int*)d_in[2];
    const int N  = in_sizes[0] / 64;
    const int E  = in_sizes[1] / 2;
    const int NC = out_size / 512;
    float* out = (float*)d_out;

    float *y0, *y1, *y2, *colsq;
    __nv_bfloat16 *w1h[3], *w1l[3], *w2h[3], *w2l[3];
    int *deg, *rowptr, *cursor, *esrc, *cdeg, *cptr, *ccur, *cnodes, *bsumsN, *bsumsC;
    cudaGetSymbolAddress((void**)&y0, g_y0);
    cudaGetSymbolAddress((void**)&y1, g_y1);
    cudaGetSymbolAddress((void**)&y2, g_y2);
    cudaGetSymbolAddress((void**)&w1h[0], g_w1thi0); cudaGetSymbolAddress((void**)&w1l[0], g_w1tlo0);
    cudaGetSymbolAddress((void**)&w1h[1], g_w1thi1); cudaGetSymbolAddress((void**)&w1l[1], g_w1tlo1);
    cudaGetSymbolAddress((void**)&w1h[2], g_w1thi2); cudaGetSymbolAddress((void**)&w1l[2], g_w1tlo2);
    cudaGetSymbolAddress((void**)&w2h[0], g_w2thi0); cudaGetSymbolAddress((void**)&w2l[0], g_w2tlo0);
    cudaGetSymbolAddress((void**)&w2h[1], g_w2thi1); cudaGetSymbolAddress((void**)&w2l[1], g_w2tlo1);
    cudaGetSymbolAddress((void**)&w2h[2], g_w2thi2); cudaGetSymbolAddress((void**)&w2l[2], g_w2tlo2);
    cudaGetSymbolAddress((void**)&colsq,  g_colsq);
    cudaGetSymbolAddress((void**)&deg,    g_deg);
    cudaGetSymbolAddress((void**)&rowptr, g_rowptr);
    cudaGetSymbolAddress((void**)&cursor, g_cursor);
    cudaGetSymbolAddress((void**)&esrc,   g_esrc);
    cudaGetSymbolAddress((void**)&cdeg,   g_cdeg);
    cudaGetSymbolAddress((void**)&cptr,   g_cptr);
    cudaGetSymbolAddress((void**)&ccur,   g_ccur);
    cudaGetSymbolAddress((void**)&cnodes, g_cnodes);
    cudaGetSymbolAddress((void**)&bsumsN, g_bsumsN);
    cudaGetSymbolAddress((void**)&bsumsC, g_bsumsC);

    const int SM64  = 2 * (64*72  + 128*72 + 64*72 ) * 2;   //  73728
    const int SM128 = 2 * (64*136 + 128*72 + 128*72) * 2;   // 108544
    const int SM256 = 2 * (64*264 + 128*72 + 256*72) * 2;   // 178176
    cudaFuncSetAttribute((const void*)fused_mlp<64, 128>,  cudaFuncAttributeMaxDynamicSharedMemorySize, SM64);
    cudaFuncSetAttribute((const void*)fused_mlp<128, 256>, cudaFuncAttributeMaxDynamicSharedMemorySize, SM128);
    cudaFuncSetAttribute((const void*)fused_mlp<256, 256>, cudaFuncAttributeMaxDynamicSharedMemorySize, SM256);

    const int GRID = (N + 127) / 128;
    const int nbN = (N + 511) / 512;
    const int nbC = (NC + 511) / 512;

    // ---- fork: CSR build on side stream, weights+mlp64 on main stream ------
    cudaStream_t sB;
    cudaStreamCreateWithFlags(&sB, cudaStreamNonBlocking);
    cudaEvent_t evA, evB;
    cudaEventCreateWithFlags(&evA, cudaEventDisableTiming);
    cudaEventCreateWithFlags(&evB, cudaEventDisableTiming);

    cudaEventRecord(evA, 0);
    cudaStreamWaitEvent(sB, evA, 0);

    // side branch: CSR build
    init_csr<<<(N + 255) / 256, 256, 0, sB>>>(deg, cursor, cdeg, ccur, colsq, N, NC);
    hist_fused<<<(E + N + 255) / 256, 256, 0, sB>>>(ei, E, cluster, N, deg, cdeg);
    scan_block2<<<nbN + nbC, 512, 0, sB>>>(deg, rowptr, bsumsN, N, nbN, cdeg, cptr, bsumsC, NC);
    scan_add_fused<<<nbN + nbC, 512, 0, sB>>>(rowptr, bsumsN, N, nbN, cptr, bsumsC, NC);
    scatter_fused<<<(E + N + 255) / 256, 256, 0, sB>>>(ei, E, cluster, N, rowptr, cursor,
                                                       esrc, cptr, ccur, cnodes);
    cudaEventRecord(evB, sB);

    // main branch: weight conversion + layer 0 MLP
    {
        WConv a;
        int off = 0;
        const int CINs[3] = {64, 128, 256};
        for (int i = 0; i < 3; i++) {
            int c = CINs[i];
            a.in[2*i]   = (const float*)d_in[3 + 6*i];
            a.hi[2*i]   = w1h[i]; a.lo[2*i] = w1l[i];
            a.K[2*i]    = c;  a.M[2*i] = 64;
            a.off[2*i]  = off; off += c * 64;
            a.in[2*i+1] = (const float*)d_in[3 + 6*i + 4];
            a.hi[2*i+1] = w2h[i]; a.lo[2*i+1] = w2l[i];
            a.K[2*i+1]  = 64; a.M[2*i+1] = c;
            a.off[2*i+1] = off; off += 64 * c;
        }
        a.off[6] = off;
        conv_weights<<<(off + 255) / 256, 256>>>(a);
    }

    fused_mlp<64, 128><<<GRID, 256, SM64>>>(
        x, w1h[0], w1l[0], (const float*)d_in[4], (const float*)d_in[5],
        (const float*)d_in[6], w2h[0], w2l[0], (const float*)d_in[8], y0, N);

    // join: agg64 needs both y0 (main) and CSR (side)
    cudaStreamWaitEvent(0, evB, 0);

    agg_f<64><<<(N + 7) / 8, 256>>>(y0, rowptr, deg, esrc, N);

    fused_mlp<128, 256><<<GRID, 256, SM128>>>(
        y0, w1h[1], w1l[1], (const float*)d_in[10], (const float*)d_in[11],
        (const float*)d_in[12], w2h[1], w2l[1], (const float*)d_in[14], y1, N);
    agg_f<128><<<(N + 7) / 8, 256>>>(y1, rowptr, deg, esrc, N);

    fused_mlp<256, 256><<<GRID, 256, SM256>>>(
        y1, w1h[2], w1l[2], (const float*)d_in[16], (const float*)d_in[17],
        (const float*)d_in[18], w2h[2], w2l[2], (const float*)d_in[20], y2, N);

    pool_agg<<<NC, 128>>>(y2, cptr, cdeg, cnodes, rowptr, deg, esrc, out);
    colsq_kernel<<<(NC + 49) / 50, 512>>>(out, colsq, NC);
    scale_kernel<<<(NC * 128 + 255) / 256, 256>>>(out, colsq, NC);
}

// round 16
// speedup vs baseline: 1.4986x; 1.0391x over previous
#include <cuda_runtime.h>
#include <cuda_bf16.h>
#include <cstdint>

#define LN_EPS 1e-5f

// ---------------- scratch (device globals: allocation-free) ----------------
__device__ __align__(128) float g_y0[100000 * 128];
__device__ __align__(128) float g_y1[100000 * 256];
__device__ __align__(128) float g_y2[100000 * 256];   // layer2 GEMM out only
__device__ __align__(128) __nv_bfloat16 g_w1thi0[64*64],  g_w1tlo0[64*64];
__device__ __align__(128) __nv_bfloat16 g_w1thi1[64*128], g_w1tlo1[64*128];
__device__ __align__(128) __nv_bfloat16 g_w1thi2[64*256], g_w1tlo2[64*256];
__device__ __align__(128) __nv_bfloat16 g_w2thi0[64*64],  g_w2tlo0[64*64];
__device__ __align__(128) __nv_bfloat16 g_w2thi1[128*64], g_w2tlo1[128*64];
__device__ __align__(128) __nv_bfloat16 g_w2thi2[256*64], g_w2tlo2[256*64];
__device__ float g_colsq[512];

// CSR scratch
__device__ int g_deg[100000];
__device__ int g_rowptr[100000];
__device__ int g_cursor[100000];
__device__ int g_esrc[800000];
__device__ int g_cdeg[10000];
__device__ int g_cptr[10000];
__device__ int g_ccur[10000];
__device__ int g_cnodes[100000];
__device__ int g_bsumsN[512];
__device__ int g_bsumsC[512];

__device__ __forceinline__ float neg_inf() { return __int_as_float(0xff800000); }

__device__ __forceinline__ void split2(float a, float b, uint32_t& hi, uint32_t& lo) {
    __nv_bfloat16 ah = __float2bfloat16_rn(a);
    __nv_bfloat16 bh = __float2bfloat16_rn(b);
    __nv_bfloat16 al = __float2bfloat16_rn(a - __bfloat162float(ah));
    __nv_bfloat16 bl = __float2bfloat16_rn(b - __bfloat162float(bh));
    __nv_bfloat162 h = __halves2bfloat162(ah, bh);
    __nv_bfloat162 l = __halves2bfloat162(al, bl);
    hi = *reinterpret_cast<uint32_t*>(&h);
    lo = *reinterpret_cast<uint32_t*>(&l);
}

__device__ __forceinline__ void mma16816(float* c, const uint32_t* a,
                                         uint32_t b0, uint32_t b1) {
    asm volatile(
        "mma.sync.aligned.m16n8k16.row.col.f32.bf16.bf16.f32 "
        "{%0,%1,%2,%3}, {%4,%5,%6,%7}, {%8,%9}, {%0,%1,%2,%3};"
        : "+f"(c[0]), "+f"(c[1]), "+f"(c[2]), "+f"(c[3])
        : "r"(a[0]), "r"(a[1]), "r"(a[2]), "r"(a[3]), "r"(b0), "r"(b1));
}

__device__ __forceinline__ uint32_t sm_off(const void* p) {
    uint32_t a;
    asm("{ .reg .u64 t; cvta.to.shared.u64 t, %1; cvt.u32.u64 %0, t; }" : "=r"(a) : "l"(p));
    return a;
}

__device__ __forceinline__ void ldsm_x4(uint32_t& r0, uint32_t& r1,
                                        uint32_t& r2, uint32_t& r3, uint32_t addr) {
    asm volatile("ldmatrix.sync.aligned.m8n8.x4.shared.b16 {%0,%1,%2,%3}, [%4];"
                 : "=r"(r0), "=r"(r1), "=r"(r2), "=r"(r3) : "r"(addr));
}

// ---------------- init kernels ----------------------------------------------
struct WConv {
    const float* in[6];
    __nv_bfloat16* hi[6];
    __nv_bfloat16* lo[6];
    int K[6], M[6];
    int off[7];
};

__global__ void conv_weights(WConv a)
{
    int gid = blockIdx.x * blockDim.x + threadIdx.x;
    if (gid >= a.off[6]) return;
    int s = 0;
#pragma unroll
    for (int i = 1; i < 6; i++) if (gid >= a.off[i]) s = i;
    int local = gid - a.off[s];
    int M = a.M[s], K = a.K[s];
    int k = local / M, m = local - k * M;
    float v = __ldg(a.in[s] + local);
    __nv_bfloat16 h = __float2bfloat16_rn(v);
    a.hi[s][m * K + k] = h;
    a.lo[s][m * K + k] = __float2bfloat16_rn(v - __bfloat162float(h));
}

__global__ void init_csr(int* __restrict__ deg, int* __restrict__ cursor,
                         int* __restrict__ cdeg, int* __restrict__ ccur,
                         float* __restrict__ colsq, int n, int nc)
{
    int gid = blockIdx.x * blockDim.x + threadIdx.x;
    if (gid < n) { deg[gid] = 0; cursor[gid] = 0; }
    if (gid < nc) { cdeg[gid] = 0; ccur[gid] = 0; }
    if (gid < 512) colsq[gid] = 0.f;
}

// ---------------- CSR build --------------------------------------------------
__global__ void hist_fused(const int* __restrict__ ei, int E,
                           const int* __restrict__ cluster, int n,
                           int* __restrict__ deg, int* __restrict__ cdeg)
{
    int gid = blockIdx.x * blockDim.x + threadIdx.x;
    if (gid < E) {
        atomicAdd(&deg[__ldg(ei + E + gid)], 1);
    } else if (gid < E + n) {
        atomicAdd(&cdeg[__ldg(cluster + gid - E)], 1);
    }
}

__global__ __launch_bounds__(512) void scan_block2(
    const int* __restrict__ inN, int* __restrict__ outN, int* __restrict__ sumsN, int n, int nbN,
    const int* __restrict__ inC, int* __restrict__ outC, int* __restrict__ sumsC, int nc)
{
    __shared__ int s[512];
    int tid = threadIdx.x;
    const int* in;  int* out; int* sums; int len; int blk;
    if ((int)blockIdx.x < nbN) { in = inN; out = outN; sums = sumsN; len = n;  blk = blockIdx.x; }
    else                       { in = inC; out = outC; sums = sumsC; len = nc; blk = blockIdx.x - nbN; }
    int i = blk * 512 + tid;
    int v = (i < len) ? in[i] : 0;
    s[tid] = v;
    __syncthreads();
#pragma unroll
    for (int off = 1; off < 512; off <<= 1) {
        int t = (tid >= off) ? s[tid - off] : 0;
        __syncthreads();
        s[tid] += t;
        __syncthreads();
    }
    if (i < len) out[i] = s[tid] - v;
    if (tid == 511) sums[blk] = s[511];
}

__global__ __launch_bounds__(512) void scan_add_fused(
    int* __restrict__ outN, const int* __restrict__ sumsN, int n, int nbN,
    int* __restrict__ outC, const int* __restrict__ sumsC, int nc)
{
    __shared__ int red[16];
    __shared__ int total;
    int tid = threadIdx.x;
    int* out; const int* sums; int len; int blk;
    if ((int)blockIdx.x < nbN) { out = outN; sums = sumsN; len = n;  blk = blockIdx.x; }
    else                       { out = outC; sums = sumsC; len = nc; blk = blockIdx.x - nbN; }
    int p = 0;
    for (int i = tid; i < blk; i += 512) p += sums[i];
#pragma unroll
    for (int off = 16; off >= 1; off >>= 1) p += __shfl_xor_sync(0xffffffffu, p, off);
    if ((tid & 31) == 0) red[tid >> 5] = p;
    __syncthreads();
    if (tid == 0) {
        int t = 0;
#pragma unroll
        for (int i = 0; i < 16; i++) t += red[i];
        total = t;
    }
    __syncthreads();
    int i = blk * 512 + tid;
    if (i < len) out[i] += total;
}

__global__ void scatter_fused(const int* __restrict__ ei, int E,
                              const int* __restrict__ cluster, int n,
                              const int* __restrict__ rowptr, int* __restrict__ cursor,
                              int* __restrict__ esrc,
                              const int* __restrict__ cptr, int* __restrict__ ccur,
                              int* __restrict__ cnodes)
{
    int gid = blockIdx.x * blockDim.x + threadIdx.x;
    if (gid < E) {
        int src = __ldg(ei + gid);
        int tgt = __ldg(ei + E + gid);
        int pos = rowptr[tgt] + atomicAdd(&cursor[tgt], 1);
        esrc[pos] = src;
    } else if (gid < E + n) {
        int i = gid - E;
        int cl = __ldg(cluster + i);
        int pos = cptr[cl] + atomicAdd(&ccur[cl], 1);
        cnodes[pos] = i;
    }
}

// ---------------- fused MLP layer: gemm1+bias+LN+ReLU+gemm2+bias ------------
// MT = M-tile rows per block (128 or 256); THREADS = 2*MT; warp owns 16 rows.
template<int C, int OS, int MT>
__global__ __launch_bounds__(MT * 2) void fused_mlp(
    const float* __restrict__ Ain,
    const __nv_bfloat16* __restrict__ W1hi, const __nv_bfloat16* __restrict__ W1lo,
    const float* __restrict__ b1, const float* __restrict__ gam,
    const float* __restrict__ bet,
    const __nv_bfloat16* __restrict__ W2hi, const __nv_bfloat16* __restrict__ W2lo,
    const float* __restrict__ b2,
    float* __restrict__ Y, int n)
{
    constexpr int THREADS = MT * 2;
    constexpr int RSTEP = THREADS / 32;   // staging row step
    constexpr int AS  = 72;
    constexpr int WS  = C + 8;
    constexpr int NKC = C / 64;
    constexpr int NG  = C / 64;
    constexpr int W1E = 64 * WS;
    constexpr int AE  = MT * AS;
    extern __shared__ __align__(16) __nv_bfloat16 sm[];
    __nv_bfloat16* W1s0 = sm;
    __nv_bfloat16* W1s1 = sm + W1E;
    __nv_bfloat16* As0  = sm + 2 * W1E;
    __nv_bfloat16* As1  = As0 + AE;
    __nv_bfloat16* W2s0 = As1 + AE;
    __nv_bfloat16* W2s1 = W2s0 + C * AS;

    const int tid = threadIdx.x, wid = tid >> 5, lane = tid & 31;
    const int g = lane >> 2, q = lane & 3;
    const int r0b = blockIdx.x * MT;

    {
        constexpr int VPR = C / 8;
        for (int i = tid; i < 64 * VPR; i += THREADS) {
            int m = i / VPR, seg = i - m * VPR;
            *(uint4*)&W1s0[m * WS + seg * 8] = __ldg((const uint4*)(W1hi + (size_t)m * C) + seg);
            *(uint4*)&W1s1[m * WS + seg * 8] = __ldg((const uint4*)(W1lo + (size_t)m * C) + seg);
        }
        for (int i = tid; i < C * 8; i += THREADS) {
            int m = i >> 3, seg = i & 7;
            *(uint4*)&W2s0[m * AS + seg * 8] = __ldg((const uint4*)(W2hi + (size_t)m * 64) + seg);
            *(uint4*)&W2s1[m * AS + seg * 8] = __ldg((const uint4*)(W2lo + (size_t)m * 64) + seg);
        }
    }

    const int arow = wid * 16 + (lane & 15);
    const int acol = ((lane >> 4) & 1) * 8;
    const uint32_t a_hi = sm_off(As0 + arow * AS + acol);
    const uint32_t a_lo = sm_off(As1 + arow * AS + acol);
    const int brow = (lane & 7) + ((lane >> 4) << 3);
    const int bk8  = ((lane >> 3) & 1) * 8;
    const uint32_t w1h_b = sm_off(W1s0 + brow * WS + bk8);
    const uint32_t w1l_b = sm_off(W1s1 + brow * WS + bk8);
    const uint32_t w2h_b = sm_off(W2s0 + brow * AS + bk8);
    const uint32_t w2l_b = sm_off(W2s1 + brow * AS + bk8);

    const int sm_m = tid >> 5;
    const int sm_e = tid & 31;

    float acc[8][4] = {};

    // stage chunk 0
    {
#pragma unroll
        for (int rpt = 0; rpt < 16; rpt++) {
            int m = sm_m + rpt * RSTEP;
            int r = r0b + m;
            uint32_t h = 0, l = 0;
            if (r < n) {
                float2 v = __ldg((const float2*)Ain + (size_t)r * (C / 2) + sm_e);
                split2(v.x, v.y, h, l);
            }
            *(uint32_t*)&As0[m * AS + 2 * sm_e] = h;
            *(uint32_t*)&As1[m * AS + 2 * sm_e] = l;
        }
    }
    __syncthreads();

    for (int kc = 0; kc < NKC; kc++) {
        float2 pf[16];
        if (kc + 1 < NKC) {
#pragma unroll
            for (int rpt = 0; rpt < 16; rpt++) {
                int m = sm_m + rpt * RSTEP;
                int r = r0b + m;
                pf[rpt] = (r < n)
                    ? __ldg((const float2*)Ain + (size_t)r * (C / 2) + (kc + 1) * 32 + sm_e)
                    : make_float2(0.f, 0.f);
            }
        }

#pragma unroll
        for (int ks = 0; ks < 4; ks++) {
            const int k0 = ks * 16;
            uint32_t ah[4], al[4];
            ldsm_x4(ah[0], ah[1], ah[2], ah[3], a_hi + k0 * 2);
            ldsm_x4(al[0], al[1], al[2], al[3], a_lo + k0 * 2);
            const int kg = kc * 64 + k0;
#pragma unroll
            for (int jj = 0; jj < 8; jj += 2) {
                uint32_t p0, p1, p2, p3, l0, l1, l2, l3;
                ldsm_x4(p0, p1, p2, p3, w1h_b + (8 * jj * WS + kg) * 2);
                ldsm_x4(l0, l1, l2, l3, w1l_b + (8 * jj * WS + kg) * 2);
                mma16816(acc[jj],     ah, p0, p1);
                mma16816(acc[jj],     ah, l0, l1);
                mma16816(acc[jj],     al, p0, p1);
                mma16816(acc[jj + 1], ah, p2, p3);
                mma16816(acc[jj + 1], ah, l2, l3);
                mma16816(acc[jj + 1], al, p2, p3);
            }
        }

        if (kc + 1 < NKC) {
            __syncthreads();
#pragma unroll
            for (int rpt = 0; rpt < 16; rpt++) {
                int m = sm_m + rpt * RSTEP;
                uint32_t h, l;
                split2(pf[rpt].x, pf[rpt].y, h, l);
                *(uint32_t*)&As0[m * AS + 2 * sm_e] = h;
                *(uint32_t*)&As1[m * AS + 2 * sm_e] = l;
            }
            __syncthreads();
        }
    }

    // ---- gemm1 epilogue: bias + LN (quad shuffle) + ReLU -> H in As --------
    {
        float v0[16], v1[16];
        float s0 = 0.f, q0 = 0.f, s1 = 0.f, q1 = 0.f;
#pragma unroll
        for (int j = 0; j < 8; j++) {
            int c0 = 8*j + 2*q;
            float bx = __ldg(b1 + c0), by = __ldg(b1 + c0 + 1);
            float a = acc[j][0] + bx, b = acc[j][1] + by;
            float c = acc[j][2] + bx, d = acc[j][3] + by;
            v0[2*j] = a; v0[2*j+1] = b; v1[2*j] = c; v1[2*j+1] = d;
            s0 += a + b; q0 += a*a + b*b;
            s1 += c + d; q1 += c*c + d*d;
        }
#pragma unroll
        for (int off = 1; off < 4; off <<= 1) {
            s0 += __shfl_xor_sync(0xffffffffu, s0, off);
            q0 += __shfl_xor_sync(0xffffffffu, q0, off);
            s1 += __shfl_xor_sync(0xffffffffu, s1, off);
            q1 += __shfl_xor_sync(0xffffffffu, q1, off);
        }
        float mu0 = s0 * (1.f/64.f), var0 = q0 * (1.f/64.f) - mu0*mu0;
        float mu1 = s1 * (1.f/64.f), var1 = q1 * (1.f/64.f) - mu1*mu1;
        float rs0 = rsqrtf(var0 + LN_EPS), rs1 = rsqrtf(var1 + LN_EPS);
        __syncthreads();
        int rl0 = wid * 16 + g, rl1 = rl0 + 8;
#pragma unroll
        for (int j = 0; j < 8; j++) {
            int c0 = 8*j + 2*q;
            float ga = __ldg(gam + c0), gb = __ldg(gam + c0 + 1);
            float ba = __ldg(bet + c0), bb = __ldg(bet + c0 + 1);
            float f0 = fmaxf((v0[2*j]   - mu0) * rs0 * ga + ba, 0.f);
            float f1 = fmaxf((v0[2*j+1] - mu0) * rs0 * gb + bb, 0.f);
            float f2 = fmaxf((v1[2*j]   - mu1) * rs1 * ga + ba, 0.f);
            float f3 = fmaxf((v1[2*j+1] - mu1) * rs1 * gb + bb, 0.f);
            uint32_t h, l;
            split2(f0, f1, h, l);
            *(uint32_t*)&As0[rl0 * AS + c0] = h;
            *(uint32_t*)&As1[rl0 * AS + c0] = l;
            split2(f2, f3, h, l);
            *(uint32_t*)&As0[rl1 * AS + c0] = h;
            *(uint32_t*)&As1[rl1 * AS + c0] = l;
        }
    }
    __syncthreads();

    // ---- gemm2: H[MT,64] @ W2 -> Y[:, 0:C] ---------------------------------
    const int rg0 = r0b + wid * 16 + g;
    const int rg1 = rg0 + 8;

#pragma unroll
    for (int ng = 0; ng < NG; ng++) {
        float acc2[8][4] = {};
#pragma unroll
        for (int ks = 0; ks < 4; ks++) {
            const int k0 = ks * 16;
            uint32_t ah[4], al[4];
            ldsm_x4(ah[0], ah[1], ah[2], ah[3], a_hi + k0 * 2);
            ldsm_x4(al[0], al[1], al[2], al[3], a_lo + k0 * 2);
#pragma unroll
            for (int jj = 0; jj < 8; jj += 2) {
                uint32_t p0, p1, p2, p3, l0, l1, l2, l3;
                ldsm_x4(p0, p1, p2, p3, w2h_b + ((ng * 64 + 8 * jj) * AS + k0) * 2);
                ldsm_x4(l0, l1, l2, l3, w2l_b + ((ng * 64 + 8 * jj) * AS + k0) * 2);
                mma16816(acc2[jj],     ah, p0, p1);
                mma16816(acc2[jj],     ah, l0, l1);
                mma16816(acc2[jj],     al, p0, p1);
                mma16816(acc2[jj + 1], ah, p2, p3);
                mma16816(acc2[jj + 1], ah, l2, l3);
                mma16816(acc2[jj + 1], al, p2, p3);
            }
        }
        if (rg0 < n) {
            float2* orow = (float2*)(Y + (size_t)rg0 * OS) + ng * 32;
#pragma unroll
            for (int j = 0; j < 8; j++) {
                int c0 = 8*j + 2*q;
                orow[4*j + q] = make_float2(acc2[j][0] + __ldg(b2 + ng*64 + c0),
                                            acc2[j][1] + __ldg(b2 + ng*64 + c0 + 1));
            }
        }
        if (rg1 < n) {
            float2* orow = (float2*)(Y + (size_t)rg1 * OS) + ng * 32;
#pragma unroll
            for (int j = 0; j < 8; j++) {
                int c0 = 8*j + 2*q;
                orow[4*j + q] = make_float2(acc2[j][2] + __ldg(b2 + ng*64 + c0),
                                            acc2[j][3] + __ldg(b2 + ng*64 + c0 + 1));
            }
        }
    }
}

// ---------------- CSR gather-max aggregation (fp32, unrolled x4) ------------
template<int C>
__global__ __launch_bounds__(256) void agg_f(
    float* __restrict__ Y, const int* __restrict__ rowptr,
    const int* __restrict__ deg, const int* __restrict__ esrc, int n)
{
    int w = (blockIdx.x * blockDim.x + threadIdx.x) >> 5;
    if (w >= n) return;
    const int lane = threadIdx.x & 31;
    constexpr int EPL = C / 64;
    float2 mx[EPL];
#pragma unroll
    for (int i = 0; i < EPL; i++) mx[i] = make_float2(neg_inf(), neg_inf());
    int d = __ldg(deg + w), base = __ldg(rowptr + w);
    int j = 0;
    for (; j + 3 < d; j += 4) {
        int s0 = __ldg(esrc + base + j);
        int s1 = __ldg(esrc + base + j + 1);
        int s2 = __ldg(esrc + base + j + 2);
        int s3 = __ldg(esrc + base + j + 3);
        const float2* r0 = (const float2*)(Y + (size_t)s0 * (2 * C));
        const float2* r1 = (const float2*)(Y + (size_t)s1 * (2 * C));
        const float2* r2 = (const float2*)(Y + (size_t)s2 * (2 * C));
        const float2* r3 = (const float2*)(Y + (size_t)s3 * (2 * C));
#pragma unroll
        for (int i = 0; i < EPL; i++) {
            float2 v0 = __ldg(r0 + lane + i * 32);
            float2 v1 = __ldg(r1 + lane + i * 32);
            float2 v2 = __ldg(r2 + lane + i * 32);
            float2 v3 = __ldg(r3 + lane + i * 32);
            float ax = fmaxf(fmaxf(v0.x, v1.x), fmaxf(v2.x, v3.x));
            float ay = fmaxf(fmaxf(v0.y, v1.y), fmaxf(v2.y, v3.y));
            mx[i].x = fmaxf(mx[i].x, ax);
            mx[i].y = fmaxf(mx[i].y, ay);
        }
    }
    for (; j < d; j++) {
        int s0 = __ldg(esrc + base + j);
        const float2* r0 = (const float2*)(Y + (size_t)s0 * (2 * C));
#pragma unroll
        for (int i = 0; i < EPL; i++) {
            float2 v0 = __ldg(r0 + lane + i * 32);
            mx[i].x = fmaxf(mx[i].x, v0.x);
            mx[i].y = fmaxf(mx[i].y, v0.y);
        }
    }
    float2* orow = (float2*)(Y + (size_t)w * (2 * C) + C);
#pragma unroll
    for (int i = 0; i < EPL; i++)
        orow[lane + i * 32] = d ? mx[i] : make_float2(0.f, 0.f);
}

// ---------------- fused layer-2 agg + cluster max-pool ----------------------
__global__ __launch_bounds__(128) void pool_agg(
    const float* __restrict__ Y,
    const int* __restrict__ cptr, const int* __restrict__ cdeg,
    const int* __restrict__ cnodes,
    const int* __restrict__ rowptr, const int* __restrict__ deg,
    const int* __restrict__ esrc,
    float* __restrict__ out)
{
    int cl = blockIdx.x, t = threadIdx.x;
    int cd = __ldg(cdeg + cl), cbase = __ldg(cptr + cl);
    float2 m0 = make_float2(neg_inf(), neg_inf());
    float2 m1 = m0;
    bool zerodeg = false;
    for (int j = 0; j < cd; j++) {
        int nd = __ldg(cnodes + cbase + j);
        const float2* row = (const float2*)(Y + (size_t)nd * 256);
        float2 v = __ldg(row + t);
        m0.x = fmaxf(m0.x, v.x); m0.y = fmaxf(m0.y, v.y);
        int d = __ldg(deg + nd), eb = __ldg(rowptr + nd);
        if (d == 0) zerodeg = true;
        int e = 0;
        for (; e + 3 < d; e += 4) {
            int s0 = __ldg(esrc + eb + e);
            int s1 = __ldg(esrc + eb + e + 1);
            int s2 = __ldg(esrc + eb + e + 2);
            int s3 = __ldg(esrc + eb + e + 3);
            float2 w0 = __ldg((const float2*)(Y + (size_t)s0 * 256) + t);
            float2 w1 = __ldg((const float2*)(Y + (size_t)s1 * 256) + t);
            float2 w2 = __ldg((const float2*)(Y + (size_t)s2 * 256) + t);
            float2 w3 = __ldg((const float2*)(Y + (size_t)s3 * 256) + t);
            m1.x = fmaxf(m1.x, fmaxf(fmaxf(w0.x, w1.x), fmaxf(w2.x, w3.x)));
            m1.y = fmaxf(m1.y, fmaxf(fmaxf(w0.y, w1.y), fmaxf(w2.y, w3.y)));
        }
        for (; e < d; e++) {
            int s0 = __ldg(esrc + eb + e);
            float2 w0 = __ldg((const float2*)(Y + (size_t)s0 * 256) + t);
            m1.x = fmaxf(m1.x, w0.x);
            m1.y = fmaxf(m1.y, w0.y);
        }
    }
    if (cd == 0) {
        m0 = make_float2(0.f, 0.f);
        m1 = m0;
    } else if (zerodeg) {
        m1.x = fmaxf(m1.x, 0.f);
        m1.y = fmaxf(m1.y, 0.f);
    }
    float2* orow = (float2*)(out + (size_t)cl * 512);
    orow[t] = m0;
    orow[t + 128] = m1;
}

// ---------------- column L2 normalize ---------------------------------------
__global__ __launch_bounds__(512) void colsq_kernel(const float* __restrict__ out,
                                                    float* __restrict__ colsq, int nc)
{
    const int ROWS = 50;
    int c  = threadIdx.x;
    int r0 = blockIdx.x * ROWS;
    int r1 = min(r0 + ROWS, nc);
    float s = 0.f;
    for (int r = r0; r < r1; r++) {
        float f = out[(size_t)r * 512 + c];
        s += f * f;
    }
    atomicAdd(colsq + c, s);
}

__global__ void scale_kernel(float* __restrict__ out, const float* __restrict__ colsq, int nc)
{
    int gid = blockIdx.x * blockDim.x + threadIdx.x;
    if (gid >= nc * 128) return;
    int c4 = gid & 127;
    float4 v = *(float4*)(out + (size_t)gid * 4);
    float4 s = *(const float4*)(colsq + c4 * 4);
    v.x *= rsqrtf(s.x); v.y *= rsqrtf(s.y);
    v.z *= rsqrtf(s.z); v.w *= rsqrtf(s.w);
    *(float4*)(out + (size_t)gid * 4) = v;
}

// ---------------- launch ----------------------------------------------------
extern "C" void kernel_launch(void* const* d_in, const int* in_sizes, int n_in,
                              void* d_out, int out_size)
{
    const float* x       = (const float*)d_in[0];
    const int*   ei      = (const int*)d_in[1];
    const int*   cluster = (const int*)d_in[2];
    const int N  = in_sizes[0] / 64;
    const int E  = in_sizes[1] / 2;
    const int NC = out_size / 512;
    float* out = (float*)d_out;

    float *y0, *y1, *y2, *colsq;
    __nv_bfloat16 *w1h[3], *w1l[3], *w2h[3], *w2l[3];
    int *deg, *rowptr, *cursor, *esrc, *cdeg, *cptr, *ccur, *cnodes, *bsumsN, *bsumsC;
    cudaGetSymbolAddress((void**)&y0, g_y0);
    cudaGetSymbolAddress((void**)&y1, g_y1);
    cudaGetSymbolAddress((void**)&y2, g_y2);
    cudaGetSymbolAddress((void**)&w1h[0], g_w1thi0); cudaGetSymbolAddress((void**)&w1l[0], g_w1tlo0);
    cudaGetSymbolAddress((void**)&w1h[1], g_w1thi1); cudaGetSymbolAddress((void**)&w1l[1], g_w1tlo1);
    cudaGetSymbolAddress((void**)&w1h[2], g_w1thi2); cudaGetSymbolAddress((void**)&w1l[2], g_w1tlo2);
    cudaGetSymbolAddress((void**)&w2h[0], g_w2thi0); cudaGetSymbolAddress((void**)&w2l[0], g_w2tlo0);
    cudaGetSymbolAddress((void**)&w2h[1], g_w2thi1); cudaGetSymbolAddress((void**)&w2l[1], g_w2tlo1);
    cudaGetSymbolAddress((void**)&w2h[2], g_w2thi2); cudaGetSymbolAddress((void**)&w2l[2], g_w2tlo2);
    cudaGetSymbolAddress((void**)&colsq,  g_colsq);
    cudaGetSymbolAddress((void**)&deg,    g_deg);
    cudaGetSymbolAddress((void**)&rowptr, g_rowptr);
    cudaGetSymbolAddress((void**)&cursor, g_cursor);
    cudaGetSymbolAddress((void**)&esrc,   g_esrc);
    cudaGetSymbolAddress((void**)&cdeg,   g_cdeg);
    cudaGetSymbolAddress((void**)&cptr,   g_cptr);
    cudaGetSymbolAddress((void**)&ccur,   g_ccur);
    cudaGetSymbolAddress((void**)&cnodes, g_cnodes);
    cudaGetSymbolAddress((void**)&bsumsN, g_bsumsN);
    cudaGetSymbolAddress((void**)&bsumsC, g_bsumsC);

    // smem: 2*(64*WS + MT*72 + C*72)*2 bytes
    const int SM64  = 2 * (64*72  + 128*72 + 64*72 ) * 2;   //  73728  (MT=128)
    const int SM128 = 2 * (64*136 + 256*72 + 128*72) * 2;   // 145408  (MT=256)
    const int SM256 = 2 * (64*264 + 256*72 + 256*72) * 2;   // 215040  (MT=256)
    cudaFuncSetAttribute((const void*)fused_mlp<64, 128, 128>,  cudaFuncAttributeMaxDynamicSharedMemorySize, SM64);
    cudaFuncSetAttribute((const void*)fused_mlp<128, 256, 256>, cudaFuncAttributeMaxDynamicSharedMemorySize, SM128);
    cudaFuncSetAttribute((const void*)fused_mlp<256, 256, 256>, cudaFuncAttributeMaxDynamicSharedMemorySize, SM256);

    const int GRID128 = (N + 127) / 128;
    const int GRID256 = (N + 255) / 256;
    const int nbN = (N + 511) / 512;
    const int nbC = (NC + 511) / 512;

    // ---- fork: CSR build on side stream, weights+mlp64 on main stream ------
    cudaStream_t sB;
    cudaStreamCreateWithFlags(&sB, cudaStreamNonBlocking);
    cudaEvent_t evA, evB;
    cudaEventCreateWithFlags(&evA, cudaEventDisableTiming);
    cudaEventCreateWithFlags(&evB, cudaEventDisableTiming);

    cudaEventRecord(evA, 0);
    cudaStreamWaitEvent(sB, evA, 0);

    init_csr<<<(N + 255) / 256, 256, 0, sB>>>(deg, cursor, cdeg, ccur, colsq, N, NC);
    hist_fused<<<(E + N + 255) / 256, 256, 0, sB>>>(ei, E, cluster, N, deg, cdeg);
    scan_block2<<<nbN + nbC, 512, 0, sB>>>(deg, rowptr, bsumsN, N, nbN, cdeg, cptr, bsumsC, NC);
    scan_add_fused<<<nbN + nbC, 512, 0, sB>>>(rowptr, bsumsN, N, nbN, cptr, bsumsC, NC);
    scatter_fused<<<(E + N + 255) / 256, 256, 0, sB>>>(ei, E, cluster, N, rowptr, cursor,
                                                       esrc, cptr, ccur, cnodes);
    cudaEventRecord(evB, sB);

    // main branch: weight conversion + layer 0 MLP
    {
        WConv a;
        int off = 0;
        const int CINs[3] = {64, 128, 256};
        for (int i = 0; i < 3; i++) {
            int c = CINs[i];
            a.in[2*i]   = (const float*)d_in[3 + 6*i];
            a.hi[2*i]   = w1h[i]; a.lo[2*i] = w1l[i];
            a.K[2*i]    = c;  a.M[2*i] = 64;
            a.off[2*i]  = off; off += c * 64;
            a.in[2*i+1] = (const float*)d_in[3 + 6*i + 4];
            a.hi[2*i+1] = w2h[i]; a.lo[2*i+1] = w2l[i];
            a.K[2*i+1]  = 64; a.M[2*i+1] = c;
            a.off[2*i+1] = off; off += 64 * c;
        }
        a.off[6] = off;
        conv_weights<<<(off + 255) / 256, 256>>>(a);
    }

    fused_mlp<64, 128, 128><<<GRID128, 256, SM64>>>(
        x, w1h[0], w1l[0], (const float*)d_in[4], (const float*)d_in[5],
        (const float*)d_in[6], w2h[0], w2l[0], (const float*)d_in[8], y0, N);

    cudaStreamWaitEvent(0, evB, 0);

    agg_f<64><<<(N + 7) / 8, 256>>>(y0, rowptr, deg, esrc, N);

    fused_mlp<128, 256, 256><<<GRID256, 512, SM128>>>(
        y0, w1h[1], w1l[1], (const float*)d_in[10], (const float*)d_in[11],
        (const float*)d_in[12], w2h[1], w2l[1], (const float*)d_in[14], y1, N);
    agg_f<128><<<(N + 7) / 8, 256>>>(y1, rowptr, deg, esrc, N);

    fused_mlp<256, 256, 256><<<GRID256, 512, SM256>>>(
        y1, w1h[2], w1l[2], (const float*)d_in[16], (const float*)d_in[17],
        (const float*)d_in[18], w2h[2], w2l[2], (const float*)d_in[20], y2, N);

    pool_agg<<<NC, 128>>>(y2, cptr, cdeg, cnodes, rowptr, deg, esrc, out);
    colsq_kernel<<<(NC + 49) / 50, 512>>>(out, colsq, NC);
    scale_kernel<<<(NC * 128 + 255) / 256, 256>>>(out, colsq, NC);
}

// round 17
// speedup vs baseline: 1.5190x; 1.0136x over previous
#include <cuda_runtime.h>
#include <cuda_bf16.h>
#include <cstdint>

#define LN_EPS 1e-5f

// ---------------- scratch (device globals: allocation-free) ----------------
__device__ __align__(128) float g_y0[100000 * 128];
__device__ __align__(128) float g_y1[100000 * 256];
__device__ __align__(128) float g_y2[100000 * 256];   // layer2 GEMM out only
__device__ __align__(128) __nv_bfloat16 g_w1thi0[64*64],  g_w1tlo0[64*64];
__device__ __align__(128) __nv_bfloat16 g_w1thi1[64*128], g_w1tlo1[64*128];
__device__ __align__(128) __nv_bfloat16 g_w1thi2[64*256], g_w1tlo2[64*256];
__device__ __align__(128) __nv_bfloat16 g_w2thi0[64*64],  g_w2tlo0[64*64];
__device__ __align__(128) __nv_bfloat16 g_w2thi1[128*64], g_w2tlo1[128*64];
__device__ __align__(128) __nv_bfloat16 g_w2thi2[256*64], g_w2tlo2[256*64];
__device__ float g_colsq[512];

// CSR scratch
__device__ int g_deg[100000];
__device__ int g_rowptr[100000];
__device__ int g_cursor[100000];
__device__ int g_esrc[800000];
__device__ int g_cdeg[10000];
__device__ int g_cptr[10000];
__device__ int g_ccur[10000];
__device__ int g_cnodes[100000];
__device__ int g_bsumsN[512];
__device__ int g_bsumsC[512];

__device__ __forceinline__ float neg_inf() { return __int_as_float(0xff800000); }

__device__ __forceinline__ void split2(float a, float b, uint32_t& hi, uint32_t& lo) {
    __nv_bfloat16 ah = __float2bfloat16_rn(a);
    __nv_bfloat16 bh = __float2bfloat16_rn(b);
    __nv_bfloat16 al = __float2bfloat16_rn(a - __bfloat162float(ah));
    __nv_bfloat16 bl = __float2bfloat16_rn(b - __bfloat162float(bh));
    __nv_bfloat162 h = __halves2bfloat162(ah, bh);
    __nv_bfloat162 l = __halves2bfloat162(al, bl);
    hi = *reinterpret_cast<uint32_t*>(&h);
    lo = *reinterpret_cast<uint32_t*>(&l);
}

__device__ __forceinline__ void mma16816(float* c, const uint32_t* a,
                                         uint32_t b0, uint32_t b1) {
    asm volatile(
        "mma.sync.aligned.m16n8k16.row.col.f32.bf16.bf16.f32 "
        "{%0,%1,%2,%3}, {%4,%5,%6,%7}, {%8,%9}, {%0,%1,%2,%3};"
        : "+f"(c[0]), "+f"(c[1]), "+f"(c[2]), "+f"(c[3])
        : "r"(a[0]), "r"(a[1]), "r"(a[2]), "r"(a[3]), "r"(b0), "r"(b1));
}

__device__ __forceinline__ uint32_t sm_off(const void* p) {
    uint32_t a;
    asm("{ .reg .u64 t; cvta.to.shared.u64 t, %1; cvt.u32.u64 %0, t; }" : "=r"(a) : "l"(p));
    return a;
}

__device__ __forceinline__ void ldsm_x4(uint32_t& r0, uint32_t& r1,
                                        uint32_t& r2, uint32_t& r3, uint32_t addr) {
    asm volatile("ldmatrix.sync.aligned.m8n8.x4.shared.b16 {%0,%1,%2,%3}, [%4];"
                 : "=r"(r0), "=r"(r1), "=r"(r2), "=r"(r3) : "r"(addr));
}

// ---------------- init kernels ----------------------------------------------
struct WConv {
    const float* in[6];
    __nv_bfloat16* hi[6];
    __nv_bfloat16* lo[6];
    int K[6], M[6];
    int off[7];
};

__global__ void conv_weights(WConv a)
{
    int gid = blockIdx.x * blockDim.x + threadIdx.x;
    if (gid >= a.off[6]) return;
    int s = 0;
#pragma unroll
    for (int i = 1; i < 6; i++) if (gid >= a.off[i]) s = i;
    int local = gid - a.off[s];
    int M = a.M[s], K = a.K[s];
    int k = local / M, m = local - k * M;
    float v = __ldg(a.in[s] + local);
    __nv_bfloat16 h = __float2bfloat16_rn(v);
    a.hi[s][m * K + k] = h;
    a.lo[s][m * K + k] = __float2bfloat16_rn(v - __bfloat162float(h));
}

__global__ void init_csr(int* __restrict__ deg, int* __restrict__ cursor,
                         int* __restrict__ cdeg, int* __restrict__ ccur,
                         float* __restrict__ colsq, int n, int nc)
{
    int gid = blockIdx.x * blockDim.x + threadIdx.x;
    if (gid < n) { deg[gid] = 0; cursor[gid] = 0; }
    if (gid < nc) { cdeg[gid] = 0; ccur[gid] = 0; }
    if (gid < 512) colsq[gid] = 0.f;
}

// ---------------- CSR build --------------------------------------------------
__global__ void hist_fused(const int* __restrict__ ei, int E,
                           const int* __restrict__ cluster, int n,
                           int* __restrict__ deg, int* __restrict__ cdeg)
{
    int gid = blockIdx.x * blockDim.x + threadIdx.x;
    if (gid < E) {
        atomicAdd(&deg[__ldg(ei + E + gid)], 1);
    } else if (gid < E + n) {
        atomicAdd(&cdeg[__ldg(cluster + gid - E)], 1);
    }
}

__global__ __launch_bounds__(512) void scan_block2(
    const int* __restrict__ inN, int* __restrict__ outN, int* __restrict__ sumsN, int n, int nbN,
    const int* __restrict__ inC, int* __restrict__ outC, int* __restrict__ sumsC, int nc)
{
    __shared__ int s[512];
    int tid = threadIdx.x;
    const int* in;  int* out; int* sums; int len; int blk;
    if ((int)blockIdx.x < nbN) { in = inN; out = outN; sums = sumsN; len = n;  blk = blockIdx.x; }
    else                       { in = inC; out = outC; sums = sumsC; len = nc; blk = blockIdx.x - nbN; }
    int i = blk * 512 + tid;
    int v = (i < len) ? in[i] : 0;
    s[tid] = v;
    __syncthreads();
#pragma unroll
    for (int off = 1; off < 512; off <<= 1) {
        int t = (tid >= off) ? s[tid - off] : 0;
        __syncthreads();
        s[tid] += t;
        __syncthreads();
    }
    if (i < len) out[i] = s[tid] - v;
    if (tid == 511) sums[blk] = s[511];
}

__global__ __launch_bounds__(512) void scan_add_fused(
    int* __restrict__ outN, const int* __restrict__ sumsN, int n, int nbN,
    int* __restrict__ outC, const int* __restrict__ sumsC, int nc)
{
    __shared__ int red[16];
    __shared__ int total;
    int tid = threadIdx.x;
    int* out; const int* sums; int len; int blk;
    if ((int)blockIdx.x < nbN) { out = outN; sums = sumsN; len = n;  blk = blockIdx.x; }
    else                       { out = outC; sums = sumsC; len = nc; blk = blockIdx.x - nbN; }
    int p = 0;
    for (int i = tid; i < blk; i += 512) p += sums[i];
#pragma unroll
    for (int off = 16; off >= 1; off >>= 1) p += __shfl_xor_sync(0xffffffffu, p, off);
    if ((tid & 31) == 0) red[tid >> 5] = p;
    __syncthreads();
    if (tid == 0) {
        int t = 0;
#pragma unroll
        for (int i = 0; i < 16; i++) t += red[i];
        total = t;
    }
    __syncthreads();
    int i = blk * 512 + tid;
    if (i < len) out[i] += total;
}

__global__ void scatter_fused(const int* __restrict__ ei, int E,
                              const int* __restrict__ cluster, int n,
                              const int* __restrict__ rowptr, int* __restrict__ cursor,
                              int* __restrict__ esrc,
                              const int* __restrict__ cptr, int* __restrict__ ccur,
                              int* __restrict__ cnodes)
{
    int gid = blockIdx.x * blockDim.x + threadIdx.x;
    if (gid < E) {
        int src = __ldg(ei + gid);
        int tgt = __ldg(ei + E + gid);
        int pos = rowptr[tgt] + atomicAdd(&cursor[tgt], 1);
        esrc[pos] = src;
    } else if (gid < E + n) {
        int i = gid - E;
        int cl = __ldg(cluster + i);
        int pos = cptr[cl] + atomicAdd(&ccur[cl], 1);
        cnodes[pos] = i;
    }
}

// ---------------- fused MLP layer: gemm1+bias+LN+ReLU+gemm2+bias ------------
// MT = M-tile rows per block; THREADS = 2*MT; warp owns 16 rows.
template<int C, int OS, int MT>
__global__ __launch_bounds__(MT * 2) void fused_mlp(
    const float* __restrict__ Ain,
    const __nv_bfloat16* __restrict__ W1hi, const __nv_bfloat16* __restrict__ W1lo,
    const float* __restrict__ b1, const float* __restrict__ gam,
    const float* __restrict__ bet,
    const __nv_bfloat16* __restrict__ W2hi, const __nv_bfloat16* __restrict__ W2lo,
    const float* __restrict__ b2,
    float* __restrict__ Y, int n)
{
    constexpr int THREADS = MT * 2;
    constexpr int RSTEP = THREADS / 32;   // staging row step
    constexpr int AS  = 72;
    constexpr int WS  = C + 8;
    constexpr int NKC = C / 64;
    constexpr int NG  = C / 64;
    constexpr int W1E = 64 * WS;
    constexpr int AE  = MT * AS;
    extern __shared__ __align__(16) __nv_bfloat16 sm[];
    __nv_bfloat16* W1s0 = sm;
    __nv_bfloat16* W1s1 = sm + W1E;
    __nv_bfloat16* As0  = sm + 2 * W1E;
    __nv_bfloat16* As1  = As0 + AE;
    __nv_bfloat16* W2s0 = As1 + AE;
    __nv_bfloat16* W2s1 = W2s0 + C * AS;

    const int tid = threadIdx.x, wid = tid >> 5, lane = tid & 31;
    const int g = lane >> 2, q = lane & 3;
    const int r0b = blockIdx.x * MT;

    {
        constexpr int VPR = C / 8;
        for (int i = tid; i < 64 * VPR; i += THREADS) {
            int m = i / VPR, seg = i - m * VPR;
            *(uint4*)&W1s0[m * WS + seg * 8] = __ldg((const uint4*)(W1hi + (size_t)m * C) + seg);
            *(uint4*)&W1s1[m * WS + seg * 8] = __ldg((const uint4*)(W1lo + (size_t)m * C) + seg);
        }
        for (int i = tid; i < C * 8; i += THREADS) {
            int m = i >> 3, seg = i & 7;
            *(uint4*)&W2s0[m * AS + seg * 8] = __ldg((const uint4*)(W2hi + (size_t)m * 64) + seg);
            *(uint4*)&W2s1[m * AS + seg * 8] = __ldg((const uint4*)(W2lo + (size_t)m * 64) + seg);
        }
    }

    const int arow = wid * 16 + (lane & 15);
    const int acol = ((lane >> 4) & 1) * 8;
    const uint32_t a_hi = sm_off(As0 + arow * AS + acol);
    const uint32_t a_lo = sm_off(As1 + arow * AS + acol);
    const int brow = (lane & 7) + ((lane >> 4) << 3);
    const int bk8  = ((lane >> 3) & 1) * 8;
    const uint32_t w1h_b = sm_off(W1s0 + brow * WS + bk8);
    const uint32_t w1l_b = sm_off(W1s1 + brow * WS + bk8);
    const uint32_t w2h_b = sm_off(W2s0 + brow * AS + bk8);
    const uint32_t w2l_b = sm_off(W2s1 + brow * AS + bk8);

    const int sm_m = tid >> 5;
    const int sm_e = tid & 31;

    float acc[8][4] = {};

    // stage chunk 0
    {
#pragma unroll
        for (int rpt = 0; rpt < 16; rpt++) {
            int m = sm_m + rpt * RSTEP;
            int r = r0b + m;
            uint32_t h = 0, l = 0;
            if (r < n) {
                float2 v = __ldg((const float2*)Ain + (size_t)r * (C / 2) + sm_e);
                split2(v.x, v.y, h, l);
            }
            *(uint32_t*)&As0[m * AS + 2 * sm_e] = h;
            *(uint32_t*)&As1[m * AS + 2 * sm_e] = l;
        }
    }
    __syncthreads();

    for (int kc = 0; kc < NKC; kc++) {
        float2 pf[16];
        if (kc + 1 < NKC) {
#pragma unroll
            for (int rpt = 0; rpt < 16; rpt++) {
                int m = sm_m + rpt * RSTEP;
                int r = r0b + m;
                pf[rpt] = (r < n)
                    ? __ldg((const float2*)Ain + (size_t)r * (C / 2) + (kc + 1) * 32 + sm_e)
                    : make_float2(0.f, 0.f);
            }
        }

#pragma unroll
        for (int ks = 0; ks < 4; ks++) {
            const int k0 = ks * 16;
            uint32_t ah[4], al[4];
            ldsm_x4(ah[0], ah[1], ah[2], ah[3], a_hi + k0 * 2);
            ldsm_x4(al[0], al[1], al[2], al[3], a_lo + k0 * 2);
            const int kg = kc * 64 + k0;
#pragma unroll
            for (int jj = 0; jj < 8; jj += 2) {
                uint32_t p0, p1, p2, p3, l0, l1, l2, l3;
                ldsm_x4(p0, p1, p2, p3, w1h_b + (8 * jj * WS + kg) * 2);
                ldsm_x4(l0, l1, l2, l3, w1l_b + (8 * jj * WS + kg) * 2);
                mma16816(acc[jj],     ah, p0, p1);
                mma16816(acc[jj],     ah, l0, l1);
                mma16816(acc[jj],     al, p0, p1);
                mma16816(acc[jj + 1], ah, p2, p3);
                mma16816(acc[jj + 1], ah, l2, l3);
                mma16816(acc[jj + 1], al, p2, p3);
            }
        }

        if (kc + 1 < NKC) {
            __syncthreads();
#pragma unroll
            for (int rpt = 0; rpt < 16; rpt++) {
                int m = sm_m + rpt * RSTEP;
                uint32_t h, l;
                split2(pf[rpt].x, pf[rpt].y, h, l);
                *(uint32_t*)&As0[m * AS + 2 * sm_e] = h;
                *(uint32_t*)&As1[m * AS + 2 * sm_e] = l;
            }
            __syncthreads();
        }
    }

    // ---- gemm1 epilogue: bias + LN (quad shuffle) + ReLU -> H in As --------
    {
        float v0[16], v1[16];
        float s0 = 0.f, q0 = 0.f, s1 = 0.f, q1 = 0.f;
#pragma unroll
        for (int j = 0; j < 8; j++) {
            int c0 = 8*j + 2*q;
            float bx = __ldg(b1 + c0), by = __ldg(b1 + c0 + 1);
            float a = acc[j][0] + bx, b = acc[j][1] + by;
            float c = acc[j][2] + bx, d = acc[j][3] + by;
            v0[2*j] = a; v0[2*j+1] = b; v1[2*j] = c; v1[2*j+1] = d;
            s0 += a + b; q0 += a*a + b*b;
            s1 += c + d; q1 += c*c + d*d;
        }
#pragma unroll
        for (int off = 1; off < 4; off <<= 1) {
            s0 += __shfl_xor_sync(0xffffffffu, s0, off);
            q0 += __shfl_xor_sync(0xffffffffu, q0, off);
            s1 += __shfl_xor_sync(0xffffffffu, s1, off);
            q1 += __shfl_xor_sync(0xffffffffu, q1, off);
        }
        float mu0 = s0 * (1.f/64.f), var0 = q0 * (1.f/64.f) - mu0*mu0;
        float mu1 = s1 * (1.f/64.f), var1 = q1 * (1.f/64.f) - mu1*mu1;
        float rs0 = rsqrtf(var0 + LN_EPS), rs1 = rsqrtf(var1 + LN_EPS);
        __syncthreads();
        int rl0 = wid * 16 + g, rl1 = rl0 + 8;
#pragma unroll
        for (int j = 0; j < 8; j++) {
            int c0 = 8*j + 2*q;
            float ga = __ldg(gam + c0), gb = __ldg(gam + c0 + 1);
            float ba = __ldg(bet + c0), bb = __ldg(bet + c0 + 1);
            float f0 = fmaxf((v0[2*j]   - mu0) * rs0 * ga + ba, 0.f);
            float f1 = fmaxf((v0[2*j+1] - mu0) * rs0 * gb + bb, 0.f);
            float f2 = fmaxf((v1[2*j]   - mu1) * rs1 * ga + ba, 0.f);
            float f3 = fmaxf((v1[2*j+1] - mu1) * rs1 * gb + bb, 0.f);
            uint32_t h, l;
            split2(f0, f1, h, l);
            *(uint32_t*)&As0[rl0 * AS + c0] = h;
            *(uint32_t*)&As1[rl0 * AS + c0] = l;
            split2(f2, f3, h, l);
            *(uint32_t*)&As0[rl1 * AS + c0] = h;
            *(uint32_t*)&As1[rl1 * AS + c0] = l;
        }
    }
    __syncthreads();

    // ---- gemm2: H[MT,64] @ W2 -> Y[:, 0:C] ---------------------------------
    const int rg0 = r0b + wid * 16 + g;
    const int rg1 = rg0 + 8;

#pragma unroll
    for (int ng = 0; ng < NG; ng++) {
        float acc2[8][4] = {};
#pragma unroll
        for (int ks = 0; ks < 4; ks++) {
            const int k0 = ks * 16;
            uint32_t ah[4], al[4];
            ldsm_x4(ah[0], ah[1], ah[2], ah[3], a_hi + k0 * 2);
            ldsm_x4(al[0], al[1], al[2], al[3], a_lo + k0 * 2);
#pragma unroll
            for (int jj = 0; jj < 8; jj += 2) {
                uint32_t p0, p1, p2, p3, l0, l1, l2, l3;
                ldsm_x4(p0, p1, p2, p3, w2h_b + ((ng * 64 + 8 * jj) * AS + k0) * 2);
                ldsm_x4(l0, l1, l2, l3, w2l_b + ((ng * 64 + 8 * jj) * AS + k0) * 2);
                mma16816(acc2[jj],     ah, p0, p1);
                mma16816(acc2[jj],     ah, l0, l1);
                mma16816(acc2[jj],     al, p0, p1);
                mma16816(acc2[jj + 1], ah, p2, p3);
                mma16816(acc2[jj + 1], ah, l2, l3);
                mma16816(acc2[jj + 1], al, p2, p3);
            }
        }
        if (rg0 < n) {
            float2* orow = (float2*)(Y + (size_t)rg0 * OS) + ng * 32;
#pragma unroll
            for (int j = 0; j < 8; j++) {
                int c0 = 8*j + 2*q;
                orow[4*j + q] = make_float2(acc2[j][0] + __ldg(b2 + ng*64 + c0),
                                            acc2[j][1] + __ldg(b2 + ng*64 + c0 + 1));
            }
        }
        if (rg1 < n) {
            float2* orow = (float2*)(Y + (size_t)rg1 * OS) + ng * 32;
#pragma unroll
            for (int j = 0; j < 8; j++) {
                int c0 = 8*j + 2*q;
                orow[4*j + q] = make_float2(acc2[j][2] + __ldg(b2 + ng*64 + c0),
                                            acc2[j][3] + __ldg(b2 + ng*64 + c0 + 1));
            }
        }
    }
}

// ---------------- CSR gather-max aggregation (fp32, unrolled x4) ------------
template<int C>
__global__ __launch_bounds__(256) void agg_f(
    float* __restrict__ Y, const int* __restrict__ rowptr,
    const int* __restrict__ deg, const int* __restrict__ esrc, int n)
{
    int w = (blockIdx.x * blockDim.x + threadIdx.x) >> 5;
    if (w >= n) return;
    const int lane = threadIdx.x & 31;
    constexpr int EPL = C / 64;
    float2 mx[EPL];
#pragma unroll
    for (int i = 0; i < EPL; i++) mx[i] = make_float2(neg_inf(), neg_inf());
    int d = __ldg(deg + w), base = __ldg(rowptr + w);
    int j = 0;
    for (; j + 3 < d; j += 4) {
        int s0 = __ldg(esrc + base + j);
        int s1 = __ldg(esrc + base + j + 1);
        int s2 = __ldg(esrc + base + j + 2);
        int s3 = __ldg(esrc + base + j + 3);
        const float2* r0 = (const float2*)(Y + (size_t)s0 * (2 * C));
        const float2* r1 = (const float2*)(Y + (size_t)s1 * (2 * C));
        const float2* r2 = (const float2*)(Y + (size_t)s2 * (2 * C));
        const float2* r3 = (const float2*)(Y + (size_t)s3 * (2 * C));
#pragma unroll
        for (int i = 0; i < EPL; i++) {
            float2 v0 = __ldg(r0 + lane + i * 32);
            float2 v1 = __ldg(r1 + lane + i * 32);
            float2 v2 = __ldg(r2 + lane + i * 32);
            float2 v3 = __ldg(r3 + lane + i * 32);
            float ax = fmaxf(fmaxf(v0.x, v1.x), fmaxf(v2.x, v3.x));
            float ay = fmaxf(fmaxf(v0.y, v1.y), fmaxf(v2.y, v3.y));
            mx[i].x = fmaxf(mx[i].x, ax);
            mx[i].y = fmaxf(mx[i].y, ay);
        }
    }
    for (; j < d; j++) {
        int s0 = __ldg(esrc + base + j);
        const float2* r0 = (const float2*)(Y + (size_t)s0 * (2 * C));
#pragma unroll
        for (int i = 0; i < EPL; i++) {
            float2 v0 = __ldg(r0 + lane + i * 32);
            mx[i].x = fmaxf(mx[i].x, v0.x);
            mx[i].y = fmaxf(mx[i].y, v0.y);
        }
    }
    float2* orow = (float2*)(Y + (size_t)w * (2 * C) + C);
#pragma unroll
    for (int i = 0; i < EPL; i++)
        orow[lane + i * 32] = d ? mx[i] : make_float2(0.f, 0.f);
}

// ---------------- fused layer-2 agg + cluster max-pool ----------------------
__global__ __launch_bounds__(128) void pool_agg(
    const float* __restrict__ Y,
    const int* __restrict__ cptr, const int* __restrict__ cdeg,
    const int* __restrict__ cnodes,
    const int* __restrict__ rowptr, const int* __restrict__ deg,
    const int* __restrict__ esrc,
    float* __restrict__ out)
{
    int cl = blockIdx.x, t = threadIdx.x;
    int cd = __ldg(cdeg + cl), cbase = __ldg(cptr + cl);
    float2 m0 = make_float2(neg_inf(), neg_inf());
    float2 m1 = m0;
    bool zerodeg = false;
    for (int j = 0; j < cd; j++) {
        int nd = __ldg(cnodes + cbase + j);
        const float2* row = (const float2*)(Y + (size_t)nd * 256);
        float2 v = __ldg(row + t);
        m0.x = fmaxf(m0.x, v.x); m0.y = fmaxf(m0.y, v.y);
        int d = __ldg(deg + nd), eb = __ldg(rowptr + nd);
        if (d == 0) zerodeg = true;
        int e = 0;
        for (; e + 3 < d; e += 4) {
            int s0 = __ldg(esrc + eb + e);
            int s1 = __ldg(esrc + eb + e + 1);
            int s2 = __ldg(esrc + eb + e + 2);
            int s3 = __ldg(esrc + eb + e + 3);
            float2 w0 = __ldg((const float2*)(Y + (size_t)s0 * 256) + t);
            float2 w1 = __ldg((const float2*)(Y + (size_t)s1 * 256) + t);
            float2 w2 = __ldg((const float2*)(Y + (size_t)s2 * 256) + t);
            float2 w3 = __ldg((const float2*)(Y + (size_t)s3 * 256) + t);
            m1.x = fmaxf(m1.x, fmaxf(fmaxf(w0.x, w1.x), fmaxf(w2.x, w3.x)));
            m1.y = fmaxf(m1.y, fmaxf(fmaxf(w0.y, w1.y), fmaxf(w2.y, w3.y)));
        }
        for (; e < d; e++) {
            int s0 = __ldg(esrc + eb + e);
            float2 w0 = __ldg((const float2*)(Y + (size_t)s0 * 256) + t);
            m1.x = fmaxf(m1.x, w0.x);
            m1.y = fmaxf(m1.y, w0.y);
        }
    }
    if (cd == 0) {
        m0 = make_float2(0.f, 0.f);
        m1 = m0;
    } else if (zerodeg) {
        m1.x = fmaxf(m1.x, 0.f);
        m1.y = fmaxf(m1.y, 0.f);
    }
    float2* orow = (float2*)(out + (size_t)cl * 512);
    orow[t] = m0;
    orow[t + 128] = m1;
}

// ---------------- column L2 normalize ---------------------------------------
__global__ __launch_bounds__(512) void colsq_kernel(const float* __restrict__ out,
                                                    float* __restrict__ colsq, int nc)
{
    const int ROWS = 50;
    int c  = threadIdx.x;
    int r0 = blockIdx.x * ROWS;
    int r1 = min(r0 + ROWS, nc);
    float s = 0.f;
    for (int r = r0; r < r1; r++) {
        float f = out[(size_t)r * 512 + c];
        s += f * f;
    }
    atomicAdd(colsq + c, s);
}

__global__ void scale_kernel(float* __restrict__ out, const float* __restrict__ colsq, int nc)
{
    int gid = blockIdx.x * blockDim.x + threadIdx.x;
    if (gid >= nc * 128) return;
    int c4 = gid & 127;
    float4 v = *(float4*)(out + (size_t)gid * 4);
    float4 s = *(const float4*)(colsq + c4 * 4);
    v.x *= rsqrtf(s.x); v.y *= rsqrtf(s.y);
    v.z *= rsqrtf(s.z); v.w *= rsqrtf(s.w);
    *(float4*)(out + (size_t)gid * 4) = v;
}

// ---------------- launch ----------------------------------------------------
extern "C" void kernel_launch(void* const* d_in, const int* in_sizes, int n_in,
                              void* d_out, int out_size)
{
    const float* x       = (const float*)d_in[0];
    const int*   ei      = (const int*)d_in[1];
    const int*   cluster = (const int*)d_in[2];
    const int N  = in_sizes[0] / 64;
    const int E  = in_sizes[1] / 2;
    const int NC = out_size / 512;
    float* out = (float*)d_out;

    float *y0, *y1, *y2, *colsq;
    __nv_bfloat16 *w1h[3], *w1l[3], *w2h[3], *w2l[3];
    int *deg, *rowptr, *cursor, *esrc, *cdeg, *cptr, *ccur, *cnodes, *bsumsN, *bsumsC;
    cudaGetSymbolAddress((void**)&y0, g_y0);
    cudaGetSymbolAddress((void**)&y1, g_y1);
    cudaGetSymbolAddress((void**)&y2, g_y2);
    cudaGetSymbolAddress((void**)&w1h[0], g_w1thi0); cudaGetSymbolAddress((void**)&w1l[0], g_w1tlo0);
    cudaGetSymbolAddress((void**)&w1h[1], g_w1thi1); cudaGetSymbolAddress((void**)&w1l[1], g_w1tlo1);
    cudaGetSymbolAddress((void**)&w1h[2], g_w1thi2); cudaGetSymbolAddress((void**)&w1l[2], g_w1tlo2);
    cudaGetSymbolAddress((void**)&w2h[0], g_w2thi0); cudaGetSymbolAddress((void**)&w2l[0], g_w2tlo0);
    cudaGetSymbolAddress((void**)&w2h[1], g_w2thi1); cudaGetSymbolAddress((void**)&w2l[1], g_w2tlo1);
    cudaGetSymbolAddress((void**)&w2h[2], g_w2thi2); cudaGetSymbolAddress((void**)&w2l[2], g_w2tlo2);
    cudaGetSymbolAddress((void**)&colsq,  g_colsq);
    cudaGetSymbolAddress((void**)&deg,    g_deg);
    cudaGetSymbolAddress((void**)&rowptr, g_rowptr);
    cudaGetSymbolAddress((void**)&cursor, g_cursor);
    cudaGetSymbolAddress((void**)&esrc,   g_esrc);
    cudaGetSymbolAddress((void**)&cdeg,   g_cdeg);
    cudaGetSymbolAddress((void**)&cptr,   g_cptr);
    cudaGetSymbolAddress((void**)&ccur,   g_ccur);
    cudaGetSymbolAddress((void**)&cnodes, g_cnodes);
    cudaGetSymbolAddress((void**)&bsumsN, g_bsumsN);
    cudaGetSymbolAddress((void**)&bsumsC, g_bsumsC);

    // smem: 2*(64*WS + MT*72 + C*72)*2 bytes
    const int SM64  = 2 * (64*72  + 256*72 + 64*72 ) * 2;   // 110592  (MT=256)
    const int SM128 = 2 * (64*136 + 256*72 + 128*72) * 2;   // 145408  (MT=256)
    const int SM256 = 2 * (64*264 + 256*72 + 256*72) * 2;   // 215040  (MT=256)
    cudaFuncSetAttribute((const void*)fused_mlp<64, 128, 256>,  cudaFuncAttributeMaxDynamicSharedMemorySize, SM64);
    cudaFuncSetAttribute((const void*)fused_mlp<128, 256, 256>, cudaFuncAttributeMaxDynamicSharedMemorySize, SM128);
    cudaFuncSetAttribute((const void*)fused_mlp<256, 256, 256>, cudaFuncAttributeMaxDynamicSharedMemorySize, SM256);

    const int GRID256 = (N + 255) / 256;
    const int nbN = (N + 511) / 512;
    const int nbC = (NC + 511) / 512;

    // ---- fork: CSR build on side stream, weights+mlp64 on main stream ------
    cudaStream_t sB;
    cudaStreamCreateWithFlags(&sB, cudaStreamNonBlocking);
    cudaEvent_t evA, evB;
    cudaEventCreateWithFlags(&evA, cudaEventDisableTiming);
    cudaEventCreateWithFlags(&evB, cudaEventDisableTiming);

    cudaEventRecord(evA, 0);
    cudaStreamWaitEvent(sB, evA, 0);

    init_csr<<<(N + 255) / 256, 256, 0, sB>>>(deg, cursor, cdeg, ccur, colsq, N, NC);
    hist_fused<<<(E + N + 255) / 256, 256, 0, sB>>>(ei, E, cluster, N, deg, cdeg);
    scan_block2<<<nbN + nbC, 512, 0, sB>>>(deg, rowptr, bsumsN, N, nbN, cdeg, cptr, bsumsC, NC);
    scan_add_fused<<<nbN + nbC, 512, 0, sB>>>(rowptr, bsumsN, N, nbN, cptr, bsumsC, NC);
    scatter_fused<<<(E + N + 255) / 256, 256, 0, sB>>>(ei, E, cluster, N, rowptr, cursor,
                                                       esrc, cptr, ccur, cnodes);
    cudaEventRecord(evB, sB);

    // main branch: weight conversion + layer 0 MLP
    {
        WConv a;
        int off = 0;
        const int CINs[3] = {64, 128, 256};
        for (int i = 0; i < 3; i++) {
            int c = CINs[i];
            a.in[2*i]   = (const float*)d_in[3 + 6*i];
            a.hi[2*i]   = w1h[i]; a.lo[2*i] = w1l[i];
            a.K[2*i]    = c;  a.M[2*i] = 64;
            a.off[2*i]  = off; off += c * 64;
            a.in[2*i+1] = (const float*)d_in[3 + 6*i + 4];
            a.hi[2*i+1] = w2h[i]; a.lo[2*i+1] = w2l[i];
            a.K[2*i+1]  = 64; a.M[2*i+1] = c;
            a.off[2*i+1] = off; off += 64 * c;
        }
        a.off[6] = off;
        conv_weights<<<(off + 255) / 256, 256>>>(a);
    }

    fused_mlp<64, 128, 256><<<GRID256, 512, SM64>>>(
        x, w1h[0], w1l[0], (const float*)d_in[4], (const float*)d_in[5],
        (const float*)d_in[6], w2h[0], w2l[0], (const float*)d_in[8], y0, N);

    cudaStreamWaitEvent(0, evB, 0);

    agg_f<64><<<(N + 7) / 8, 256>>>(y0, rowptr, deg, esrc, N);

    fused_mlp<128, 256, 256><<<GRID256, 512, SM128>>>(
        y0, w1h[1], w1l[1], (const float*)d_in[10], (const float*)d_in[11],
        (const float*)d_in[12], w2h[1], w2l[1], (const float*)d_in[14], y1, N);
    agg_f<128><<<(N + 7) / 8, 256>>>(y1, rowptr, deg, esrc, N);

    fused_mlp<256, 256, 256><<<GRID256, 512, SM256>>>(
        y1, w1h[2], w1l[2], (const float*)d_in[16], (const float*)d_in[17],
        (const float*)d_in[18], w2h[2], w2l[2], (const float*)d_in[20], y2, N);

    pool_agg<<<NC, 128>>>(y2, cptr, cdeg, cnodes, rowptr, deg, esrc, out);
    colsq_kernel<<<(NC + 49) / 50, 512>>>(out, colsq, NC);
    scale_kernel<<<(NC * 128 + 255) / 256, 256>>>(out, colsq, NC);
}